// round 3
// baseline (speedup 1.0000x reference)
#include <cuda_runtime.h>
#include <math.h>

#define Dd 256
#define Kk 64
#define Nn 64
#define Ll 4096
#define LT 64
#define LP 68
#define AP 68
#define SPLITS 4
#define CHUNK (Ll / SPLITS)
#define NT 256

// Shared memory layout (floats):
//  Ws  : Dd*Kk   = 16384   (W transposed: Ws[d*64+k])
//  Xs  : Dd*LP   = 17408   (X tile, pitch 68 to avoid column bank conflicts)
//  As  : Kk*AP   = 4352    (logits / softmax probs)
//  nrm : 256, rinv: 64, mx: 64, sinv: 64
#define SMEM_FLOATS (Dd * Kk + Dd * LP + Kk * AP + 256 + 64 + 64 + 64)
#define SMEM_BYTES (SMEM_FLOATS * 4)

__device__ float g_S1[Nn][Kk][Dd];   // sum_l a[n,k,l] * xhat[n,d,l]
__device__ float g_S2[Nn][Kk];       // sum_l a[n,k,l]

__global__ void netvlad_zero_kernel() {
    float* p1 = &g_S1[0][0][0];
    size_t n1 = (size_t)Nn * Kk * Dd;
    for (size_t i = (size_t)blockIdx.x * blockDim.x + threadIdx.x; i < n1;
         i += (size_t)gridDim.x * blockDim.x)
        p1[i] = 0.0f;
    float* p2 = &g_S2[0][0];
    size_t n2 = (size_t)Nn * Kk;
    for (size_t i = (size_t)blockIdx.x * blockDim.x + threadIdx.x; i < n2;
         i += (size_t)gridDim.x * blockDim.x)
        p2[i] = 0.0f;
}

__global__ __launch_bounds__(NT, 1)
void netvlad_main(const float* __restrict__ x, const float* __restrict__ w) {
    extern __shared__ float sh[];
    float* Ws   = sh;                  // [Dd][Kk]
    float* Xs   = Ws + Dd * Kk;        // [Dd][LP]
    float* As   = Xs + Dd * LP;        // [Kk][AP]
    float* nrm  = As + Kk * AP;        // [256]
    float* rinv = nrm + 256;           // [64]
    float* mx   = rinv + 64;           // [64]
    float* sinv = mx + 64;             // [64]

    const int tid   = threadIdx.x;
    const int n     = blockIdx.y;
    const int split = blockIdx.x;
    const float* __restrict__ xn = x + (size_t)n * Dd * Ll;

    // Load W transposed into shared: Ws[d*Kk + k] = w[k*Dd + d]
    for (int i = tid; i < Kk * Dd; i += NT) {
        int k = i >> 8;        // i / 256
        int d = i & 255;       // i % 256
        Ws[d * Kk + k] = w[i];
    }

    const int tk = tid >> 4;   // 0..15 -> owns k = 4*tk .. 4*tk+3
    const int tl = tid & 15;   // 0..15 -> owns p = 4*tl..  (GEMM1), d = tl+16*j (GEMM2)

    float acc[4][16];          // S1 slice: [k=4tk+i][d=tl+16*j]
#pragma unroll
    for (int i = 0; i < 4; i++)
#pragma unroll
        for (int j = 0; j < 16; j++) acc[i][j] = 0.0f;
    float s2acc = 0.0f;        // used by tid < 64 (k = tid)

    for (int tile = 0; tile < CHUNK / LT; ++tile) {
        const int l0 = split * CHUNK + tile * LT;
        __syncthreads();  // previous tile's GEMM2 reads done before overwriting Xs/As

        // ---- Load X tile [Dd][LT] (float4, coalesced along l) ----
        for (int idx = tid; idx < Dd * (LT / 4); idx += NT) {
            int d  = idx >> 4;
            int p4 = (idx & 15) << 2;
            float4 v = *reinterpret_cast<const float4*>(xn + (size_t)d * Ll + l0 + p4);
            *reinterpret_cast<float4*>(&Xs[d * LP + p4]) = v;
        }
        __syncthreads();

        // ---- Per-pixel L2 norm over D ----
        {
            int seg = tid >> 6, p = tid & 63;
            float s = 0.0f;
            int dbase = seg * 64;
#pragma unroll 8
            for (int d = 0; d < 64; ++d) {
                float v = Xs[(dbase + d) * LP + p];
                s += v * v;
            }
            nrm[tid] = s;
        }
        __syncthreads();
        if (tid < 64) {
            float t = nrm[tid] + nrm[64 + tid] + nrm[128 + tid] + nrm[192 + tid];
            rinv[tid] = 1.0f / fmaxf(sqrtf(t), 1e-12f);
        }
        __syncthreads();
        // scale tile in place -> xhat
        for (int i = tid; i < Dd * LT; i += NT) {
            int d = i >> 6, p = i & 63;
            Xs[d * LP + p] *= rinv[p];
        }
        __syncthreads();

        // ---- GEMM1: logits[4tk+i][4tl+j] = sum_d W[k,d] * xhat[d,p] ----
        float lg[4][4];
#pragma unroll
        for (int i = 0; i < 4; i++)
#pragma unroll
            for (int j = 0; j < 4; j++) lg[i][j] = 0.0f;
#pragma unroll 4
        for (int d = 0; d < Dd; ++d) {
            float4 wv = *reinterpret_cast<const float4*>(&Ws[d * Kk + 4 * tk]);
            float4 xv = *reinterpret_cast<const float4*>(&Xs[d * LP + 4 * tl]);
            lg[0][0] += wv.x * xv.x; lg[0][1] += wv.x * xv.y; lg[0][2] += wv.x * xv.z; lg[0][3] += wv.x * xv.w;
            lg[1][0] += wv.y * xv.x; lg[1][1] += wv.y * xv.y; lg[1][2] += wv.y * xv.z; lg[1][3] += wv.y * xv.w;
            lg[2][0] += wv.z * xv.x; lg[2][1] += wv.z * xv.y; lg[2][2] += wv.z * xv.z; lg[2][3] += wv.z * xv.w;
            lg[3][0] += wv.w * xv.x; lg[3][1] += wv.w * xv.y; lg[3][2] += wv.w * xv.z; lg[3][3] += wv.w * xv.w;
        }
#pragma unroll
        for (int i = 0; i < 4; i++)
            *reinterpret_cast<float4*>(&As[(4 * tk + i) * AP + 4 * tl]) =
                make_float4(lg[i][0], lg[i][1], lg[i][2], lg[i][3]);
        __syncthreads();

        // ---- Softmax over k for each pixel p ----
        {
            int tq = tid >> 6, p = tid & 63;
            float m = -1e30f;
            int kb = tq * 16;
#pragma unroll 4
            for (int k = 0; k < 16; ++k) m = fmaxf(m, As[(kb + k) * AP + p]);
            nrm[tid] = m;
        }
        __syncthreads();
        if (tid < 64) {
            float m = fmaxf(fmaxf(nrm[tid], nrm[64 + tid]),
                            fmaxf(nrm[128 + tid], nrm[192 + tid]));
            mx[tid] = m;
        }
        __syncthreads();
        {
            int tq = tid >> 6, p = tid & 63;
            float m = mx[p];
            float s = 0.0f;
            int kb = tq * 16;
#pragma unroll 4
            for (int k = 0; k < 16; ++k) {
                float e = __expf(As[(kb + k) * AP + p] - m);
                As[(kb + k) * AP + p] = e;
                s += e;
            }
            nrm[tid] = s;
        }
        __syncthreads();
        if (tid < 64) {
            float s = nrm[tid] + nrm[64 + tid] + nrm[128 + tid] + nrm[192 + tid];
            sinv[tid] = 1.0f / s;
        }
        __syncthreads();
        for (int i = tid; i < Kk * LT; i += NT) {
            int k = i >> 6, p = i & 63;
            As[k * AP + p] *= sinv[p];
        }
        __syncthreads();

        // S2 partial sums (k = tid)
        if (tid < 64) {
            float s = 0.0f;
#pragma unroll 8
            for (int p = 0; p < 64; ++p) s += As[tid * AP + p];
            s2acc += s;
        }

        // ---- GEMM2: acc[k][d] += sum_p a[k,p] * xhat[d,p] ----
#pragma unroll 1
        for (int pc = 0; pc < LT; pc += 4) {
            float4 av[4];
#pragma unroll
            for (int i = 0; i < 4; i++)
                av[i] = *reinterpret_cast<const float4*>(&As[(4 * tk + i) * AP + pc]);
#pragma unroll
            for (int jh = 0; jh < 2; ++jh) {
                float4 xr[8];
#pragma unroll
                for (int j = 0; j < 8; j++)
                    xr[j] = *reinterpret_cast<const float4*>(
                        &Xs[(tl + 16 * (jh * 8 + j)) * LP + pc]);
#pragma unroll
                for (int i = 0; i < 4; i++) {
#pragma unroll
                    for (int j = 0; j < 8; j++) {
                        float a0 = acc[i][jh * 8 + j];
                        a0 += av[i].x * xr[j].x;
                        a0 += av[i].y * xr[j].y;
                        a0 += av[i].z * xr[j].z;
                        a0 += av[i].w * xr[j].w;
                        acc[i][jh * 8 + j] = a0;
                    }
                }
            }
        }
    }

    // ---- Flush partials ----
#pragma unroll
    for (int i = 0; i < 4; i++)
#pragma unroll
        for (int j = 0; j < 16; j++)
            atomicAdd(&g_S1[n][4 * tk + i][tl + 16 * j], acc[i][j]);
    if (tid < 64) atomicAdd(&g_S2[n][tid], s2acc);
}

__global__ __launch_bounds__(256)
void netvlad_finalize(const float* __restrict__ cent, float* __restrict__ out) {
    const int n = blockIdx.x;
    const int d = threadIdx.x;      // 0..255, one d per thread
    const int lane = d & 31, wid = d >> 5;
    __shared__ float red[8];
    __shared__ float tot;

    float val[Kk];
    float gsum = 0.0f;

    for (int k = 0; k < Kk; ++k) {
        float v = g_S1[n][k][d] - g_S2[n][k] * cent[k * Dd + d];
        float s = v * v;
#pragma unroll
        for (int o = 16; o > 0; o >>= 1) s += __shfl_down_sync(0xffffffffu, s, o);
        if (lane == 0) red[wid] = s;
        __syncthreads();
        if (d == 0) {
            float t = 0.0f;
#pragma unroll
            for (int w2 = 0; w2 < 8; w2++) t += red[w2];
            tot = t;
        }
        __syncthreads();
        float inv = 1.0f / fmaxf(sqrtf(tot), 1e-12f);
        v *= inv;
        val[k] = v;
        gsum += v * v;
    }

#pragma unroll
    for (int o = 16; o > 0; o >>= 1) gsum += __shfl_down_sync(0xffffffffu, gsum, o);
    if (lane == 0) red[wid] = gsum;
    __syncthreads();
    if (d == 0) {
        float t = 0.0f;
#pragma unroll
        for (int w2 = 0; w2 < 8; w2++) t += red[w2];
        tot = 1.0f / fmaxf(sqrtf(t), 1e-12f);
    }
    __syncthreads();
    float ginv = tot;

    size_t base = (size_t)n * Kk * Dd;
#pragma unroll 4
    for (int k = 0; k < Kk; ++k)
        out[base + k * Dd + d] = val[k] * ginv;
}

extern "C" void kernel_launch(void* const* d_in, const int* in_sizes, int n_in,
                              void* d_out, int out_size) {
    const float* x = (const float*)d_in[0];
    const float* w = (const float*)d_in[1];
    const float* c = (const float*)d_in[2];
    float* out = (float*)d_out;

    cudaFuncSetAttribute(netvlad_main,
                         cudaFuncAttributeMaxDynamicSharedMemorySize, SMEM_BYTES);

    netvlad_zero_kernel<<<2048, 256>>>();

    dim3 grid(SPLITS, Nn);
    netvlad_main<<<grid, NT, SMEM_BYTES>>>(x, w);

    netvlad_finalize<<<Nn, 256>>>(c, out);
}

// round 6
// speedup vs baseline: 1.5187x; 1.5187x over previous
#include <cuda_runtime.h>
#include <cuda_bf16.h>
#include <cstdint>
#include <math.h>

#define Nn 64
#define Kk 64
#define Dd 256
#define Ll 4096
#define NTILES 32

// ---- smem layout (bytes); all pitches chosen so row stride % 128 == 16 ----
#define XH_OFF   0        // xhat hi  [256 d][72 p] bf16 (pitch 144B)
#define XL_OFF   36864    // xhat lo
#define WH_OFF   73728    // W hi [64 k][264 d] bf16 (pitch 528B)
#define WL_OFF   107520   // W lo
#define PAH_OFF  141312   // probs hi [64 k][72 p] bf16 (pitch 144B)
#define PAL_OFF  150528   // probs lo
#define LS_OFF   159744   // logits [64 p][68 k] f32 (pitch 272B)
#define NRM_OFF  177152   // float[256]
#define RINV_OFF 178176   // float[64]
#define SMEM_TOTAL 178432

#define XLd  (XL_OFF - XH_OFF)
#define WLd  (WL_OFF - WH_OFF)
#define PALd (PAL_OFF - PAH_OFF)

__device__ float g_S1p[2][Nn][Kk][Dd];
__device__ float g_S2p[2][Nn][Kk];

static __device__ __forceinline__ uint32_t smem_u32(const void* p) {
    uint32_t a;
    asm("{ .reg .u64 t; cvta.to.shared.u64 t, %1; cvt.u32.u64 %0, t; }" : "=r"(a) : "l"(p));
    return a;
}

static __device__ __forceinline__ void ldsm4(uint32_t r[4], uint32_t a) {
    asm volatile("ldmatrix.sync.aligned.m8n8.x4.shared.b16 {%0,%1,%2,%3}, [%4];"
                 : "=r"(r[0]), "=r"(r[1]), "=r"(r[2]), "=r"(r[3]) : "r"(a));
}
static __device__ __forceinline__ void ldsm4t(uint32_t r[4], uint32_t a) {
    asm volatile("ldmatrix.sync.aligned.m8n8.x4.trans.shared.b16 {%0,%1,%2,%3}, [%4];"
                 : "=r"(r[0]), "=r"(r[1]), "=r"(r[2]), "=r"(r[3]) : "r"(a));
}
static __device__ __forceinline__ void mma_bf16(float c[4], const uint32_t a[4],
                                                uint32_t b0, uint32_t b1) {
    asm volatile(
        "mma.sync.aligned.m16n8k16.row.col.f32.bf16.bf16.f32 "
        "{%0,%1,%2,%3},{%4,%5,%6,%7},{%8,%9},{%0,%1,%2,%3};"
        : "+f"(c[0]), "+f"(c[1]), "+f"(c[2]), "+f"(c[3])
        : "r"(a[0]), "r"(a[1]), "r"(a[2]), "r"(a[3]), "r"(b0), "r"(b1));
}

__global__ __launch_bounds__(256, 1)
void netvlad_mma(const float* __restrict__ x, const float* __restrict__ w) {
    extern __shared__ char sm[];
    const uint32_t sb = smem_u32(sm);
    const int tid = threadIdx.x;
    const int wid = tid >> 5;
    const int lane = tid & 31;
    const int n  = blockIdx.x >> 1;
    const int hf = blockIdx.x & 1;
    const int p  = tid & 63;
    const int db = tid >> 6;

    float* nrm  = (float*)(sm + NRM_OFF);
    float* rinv = (float*)(sm + RINV_OFF);
    float* Lsp  = (float*)(sm + LS_OFF);

    // ---- load + split W: WH/WL [k][d], pitch 264 bf16 ----
    for (int i = tid; i < Kk * Dd; i += 256) {
        int k = i >> 8, d = i & 255;
        float v = w[i];
        __nv_bfloat16 hi = __float2bfloat16(v);
        __nv_bfloat16 lo = __float2bfloat16(v - __bfloat162float(hi));
        *(__nv_bfloat16*)(sm + WH_OFF + k * 528 + 2 * d) = hi;
        *(__nv_bfloat16*)(sm + WL_OFF + k * 528 + 2 * d) = lo;
    }

    // GEMM2 accumulators: warp tile [64 d][32 k] -> 4x4 frags x 4 f32
    const int d0 = (wid >> 1) * 64;
    const int kq = (wid & 1) * 32;
    float acc[4][4][4];
#pragma unroll
    for (int i = 0; i < 4; i++)
#pragma unroll
        for (int j = 0; j < 4; j++)
#pragma unroll
            for (int q = 0; q < 4; q++) acc[i][j][q] = 0.0f;
    float s2acc = 0.0f;

    const float* xbase = x + ((size_t)n * Dd + db * 64) * Ll + (size_t)hf * 2048 + p;

    // GEMM1 warp tile: [16 p][32 k]
    const int p0  = (wid >> 1) * 16;
    const int k0w = (wid & 1) * 32;
    // A (trans) address: rows d, 16B block = 8 p's
    const uint32_t aA1 = sb + XH_OFF +
        ((lane & 7) + ((lane >> 4) << 3)) * 144 + (p0 + ((lane >> 3) & 1) * 8) * 2;
    // B address: rows k, 16B block = 8 d's
    const uint32_t aB1 = sb + WH_OFF + (k0w + (lane & 15)) * 528 + ((lane >> 4) << 4);
    // GEMM2 addresses
    const uint32_t aA2 = sb + XH_OFF + (d0 + (lane & 15)) * 144 + ((lane >> 4) << 4);
    const uint32_t aB2 = sb + PAH_OFF + (kq + (lane & 15)) * 144 + ((lane >> 4) << 4);

    const int g  = lane >> 2;
    const int tg = lane & 3;

    for (int tile = 0; tile < NTILES; ++tile) {
        // ---- 1: load x slice (64 d-values for pixel p), coalesced ----
        const float* src = xbase + tile * 64;
        float xr[64];
#pragma unroll 8
        for (int j = 0; j < 64; ++j) xr[j] = src[(size_t)j * Ll];
        float s = 0.0f;
#pragma unroll
        for (int j = 0; j < 64; ++j) s += xr[j] * xr[j];
        nrm[tid] = s;
        __syncthreads();
        if (tid < 64) {
            float t = nrm[tid] + nrm[64 + tid] + nrm[128 + tid] + nrm[192 + tid];
            rinv[tid] = 1.0f / fmaxf(sqrtf(t), 1e-12f);
        }
        __syncthreads();
        const float ri = rinv[p];

        // ---- 2: convert + store xhat hi/lo [d][p] ----
#pragma unroll 8
        for (int j = 0; j < 64; ++j) {
            int d = db * 64 + j;
            float v = xr[j] * ri;
            __nv_bfloat16 hi = __float2bfloat16(v);
            __nv_bfloat16 lo = __float2bfloat16(v - __bfloat162float(hi));
            *(__nv_bfloat16*)(sm + XH_OFF + d * 144 + 2 * p) = hi;
            *(__nv_bfloat16*)(sm + XL_OFF + d * 144 + 2 * p) = lo;
        }
        __syncthreads();

        // ---- 3: GEMM1 logits[p][k] = xhat^T @ W^T (contraction d) ----
        {
            float lacc[4][4];
#pragma unroll
            for (int j = 0; j < 4; j++)
#pragma unroll
                for (int q = 0; q < 4; q++) lacc[j][q] = 0.0f;
#pragma unroll 4
            for (int ks = 0; ks < 16; ++ks) {
                uint32_t Ah[4], Al[4], B0h[4], B1h[4], B0l[4], B1l[4];
                ldsm4t(Ah, aA1 + ks * 2304);
                ldsm4t(Al, aA1 + XLd + ks * 2304);
                ldsm4(B0h, aB1 + ks * 32);
                ldsm4(B1h, aB1 + 16 * 528 + ks * 32);
                ldsm4(B0l, aB1 + WLd + ks * 32);
                ldsm4(B1l, aB1 + WLd + 16 * 528 + ks * 32);
                mma_bf16(lacc[0], Ah, B0h[0], B0h[2]);
                mma_bf16(lacc[0], Al, B0h[0], B0h[2]);
                mma_bf16(lacc[0], Ah, B0l[0], B0l[2]);
                mma_bf16(lacc[1], Ah, B0h[1], B0h[3]);
                mma_bf16(lacc[1], Al, B0h[1], B0h[3]);
                mma_bf16(lacc[1], Ah, B0l[1], B0l[3]);
                mma_bf16(lacc[2], Ah, B1h[0], B1h[2]);
                mma_bf16(lacc[2], Al, B1h[0], B1h[2]);
                mma_bf16(lacc[2], Ah, B1l[0], B1l[2]);
                mma_bf16(lacc[3], Ah, B1h[1], B1h[3]);
                mma_bf16(lacc[3], Al, B1h[1], B1h[3]);
                mma_bf16(lacc[3], Ah, B1l[1], B1l[3]);
            }
#pragma unroll
            for (int j = 0; j < 4; ++j) {
                int kk = k0w + 8 * j + tg * 2;
                *(float2*)&Lsp[(p0 + g) * 68 + kk]     = make_float2(lacc[j][0], lacc[j][1]);
                *(float2*)&Lsp[(p0 + 8 + g) * 68 + kk] = make_float2(lacc[j][2], lacc[j][3]);
            }
        }
        __syncthreads();

        // ---- 4: softmax over k (thread p owns pixel p) ----
        if (tid < 64) {
            const float* row = Lsp + tid * 68;
            float e[64];
            float m = -1e30f;
#pragma unroll 8
            for (int k = 0; k < 64; ++k) { e[k] = row[k]; m = fmaxf(m, e[k]); }
            float ssum = 0.0f;
#pragma unroll 8
            for (int k = 0; k < 64; ++k) { e[k] = __expf(e[k] - m); ssum += e[k]; }
            float inv = 1.0f / ssum;
#pragma unroll 8
            for (int k = 0; k < 64; ++k) {
                float av = e[k] * inv;
                __nv_bfloat16 hi = __float2bfloat16(av);
                __nv_bfloat16 lo = __float2bfloat16(av - __bfloat162float(hi));
                *(__nv_bfloat16*)(sm + PAH_OFF + k * 144 + 2 * tid) = hi;
                *(__nv_bfloat16*)(sm + PAL_OFF + k * 144 + 2 * tid) = lo;
            }
        }
        __syncthreads();

        // ---- 5: S2 partials (threads 64..127, k = tid-64) ----
        if (tid >= 64 && tid < 128) {
            int k = tid - 64;
            const uint32_t* rh = (const uint32_t*)(sm + PAH_OFF + k * 144);
            const uint32_t* rl = (const uint32_t*)(sm + PAL_OFF + k * 144);
            float a = 0.0f;
#pragma unroll 8
            for (int c = 0; c < 32; ++c) {
                uint32_t vh = rh[c], vl = rl[c];
                __nv_bfloat162 bh = *(__nv_bfloat162*)&vh;
                __nv_bfloat162 bl = *(__nv_bfloat162*)&vl;
                a += __bfloat162float(bh.x) + __bfloat162float(bh.y) +
                     __bfloat162float(bl.x) + __bfloat162float(bl.y);
            }
            s2acc += a;
        }

        // ---- 6: GEMM2 acc[d][k] += xhat @ probs^T (contraction p) ----
#pragma unroll
        for (int ps = 0; ps < 4; ++ps) {
            uint32_t B0h[4], B1h[4], B0l[4], B1l[4];
            ldsm4(B0h, aB2 + ps * 32);
            ldsm4(B1h, aB2 + 16 * 144 + ps * 32);
            ldsm4(B0l, aB2 + PALd + ps * 32);
            ldsm4(B1l, aB2 + PALd + 16 * 144 + ps * 32);
#pragma unroll
            for (int i = 0; i < 4; ++i) {
                uint32_t Ah[4], Al[4];
                ldsm4(Ah, aA2 + i * 2304 + ps * 32);
                ldsm4(Al, aA2 + XLd + i * 2304 + ps * 32);
                mma_bf16(acc[i][0], Ah, B0h[0], B0h[2]);
                mma_bf16(acc[i][0], Al, B0h[0], B0h[2]);
                mma_bf16(acc[i][0], Ah, B0l[0], B0l[2]);
                mma_bf16(acc[i][1], Ah, B0h[1], B0h[3]);
                mma_bf16(acc[i][1], Al, B0h[1], B0h[3]);
                mma_bf16(acc[i][1], Ah, B0l[1], B0l[3]);
                mma_bf16(acc[i][2], Ah, B1h[0], B1h[2]);
                mma_bf16(acc[i][2], Al, B1h[0], B1h[2]);
                mma_bf16(acc[i][2], Ah, B1l[0], B1l[2]);
                mma_bf16(acc[i][3], Ah, B1h[1], B1h[3]);
                mma_bf16(acc[i][3], Al, B1h[1], B1h[3]);
                mma_bf16(acc[i][3], Ah, B1l[1], B1l[3]);
            }
        }
        // no trailing sync needed: next tile's first sync (after nrm store)
        // is a full barrier before any operand buffer is overwritten
    }

    // ---- flush: transpose via smem (reuse XH region), coalesced global write ----
    __syncthreads();
    float* stg = (float*)(sm + XH_OFF);   // [64 k][260 d] f32
#pragma unroll
    for (int i = 0; i < 4; ++i)
#pragma unroll
        for (int j = 0; j < 4; ++j) {
            int d  = d0 + 16 * i + g;
            int kk = kq + 8 * j + tg * 2;
            stg[kk * 260 + d]           = acc[i][j][0];
            stg[(kk + 1) * 260 + d]     = acc[i][j][1];
            stg[kk * 260 + d + 8]       = acc[i][j][2];
            stg[(kk + 1) * 260 + d + 8] = acc[i][j][3];
        }
    __syncthreads();
    {
        int k  = tid >> 2;
        int dq = (tid & 3) * 64;
#pragma unroll
        for (int jj = 0; jj < 16; ++jj) {
            float4 v = *(float4*)&stg[k * 260 + dq + jj * 4];
            *(float4*)&g_S1p[hf][n][k][dq + jj * 4] = v;
        }
    }
    if (tid >= 64 && tid < 128) g_S2p[hf][n][tid - 64] = s2acc;
}

__global__ __launch_bounds__(256)
void netvlad_finalize(const float* __restrict__ cent, float* __restrict__ out) {
    const int n = blockIdx.x;
    const int tid = threadIdx.x;
    const int w8 = tid >> 5, lane = tid & 31;
    __shared__ float s2s[64];
    __shared__ float wsum[8];
    __shared__ float ginv_s;

    if (tid < 64) s2s[tid] = g_S2p[0][n][tid] + g_S2p[1][n][tid];
    __syncthreads();

    float v[8][8];
    float gs = 0.0f;
#pragma unroll
    for (int kk = 0; kk < 8; ++kk) {
        int k = w8 * 8 + kk;
        float s2 = s2s[k];
        float loc = 0.0f;
#pragma unroll
        for (int j = 0; j < 8; ++j) {
            int d = j * 32 + lane;
            float a = g_S1p[0][n][k][d] + g_S1p[1][n][k][d] - s2 * cent[k * Dd + d];
            v[kk][j] = a;
            loc += a * a;
        }
#pragma unroll
        for (int o = 16; o > 0; o >>= 1) loc += __shfl_xor_sync(0xffffffffu, loc, o);
        float inv = 1.0f / fmaxf(sqrtf(loc), 1e-12f);
#pragma unroll
        for (int j = 0; j < 8; ++j) { v[kk][j] *= inv; gs += v[kk][j] * v[kk][j]; }
    }
#pragma unroll
    for (int o = 16; o > 0; o >>= 1) gs += __shfl_xor_sync(0xffffffffu, gs, o);
    if (lane == 0) wsum[w8] = gs;
    __syncthreads();
    if (tid == 0) {
        float t = 0.0f;
#pragma unroll
        for (int i = 0; i < 8; ++i) t += wsum[i];
        ginv_s = 1.0f / fmaxf(sqrtf(t), 1e-12f);
    }
    __syncthreads();
    float gi = ginv_s;
    size_t base = (size_t)n * Kk * Dd;
#pragma unroll
    for (int kk = 0; kk < 8; ++kk) {
        int k = w8 * 8 + kk;
#pragma unroll
        for (int j = 0; j < 8; ++j)
            out[base + (size_t)k * Dd + j * 32 + lane] = v[kk][j] * gi;
    }
}

extern "C" void kernel_launch(void* const* d_in, const int* in_sizes, int n_in,
                              void* d_out, int out_size) {
    const float* x = (const float*)d_in[0];
    const float* w = (const float*)d_in[1];
    const float* c = (const float*)d_in[2];
    float* out = (float*)d_out;

    cudaFuncSetAttribute(netvlad_mma,
                         cudaFuncAttributeMaxDynamicSharedMemorySize, SMEM_TOTAL);

    netvlad_mma<<<2 * Nn, 256, SMEM_TOTAL>>>(x, w);
    netvlad_finalize<<<Nn, 256>>>(c, out);
}

// round 7
// speedup vs baseline: 1.7723x; 1.1670x over previous
#include <cuda_runtime.h>
#include <cuda_fp16.h>
#include <cstdint>
#include <math.h>

#define Nn 64
#define Kk 64
#define Dd 256
#define Ll 4096
#define NTILES 32

// ---- smem layout (bytes); pitches % 128 == 16 for conflict-free ldmatrix ----
#define XH_OFF   0        // xhat hi  [256 d][72 p] f16 (pitch 144B)
#define XL_OFF   36864    // xhat lo
#define WH_OFF   73728    // W hi [64 k][264 d] f16 (pitch 528B)
#define PAH_OFF  107520   // probs hi [64 k][72 p] f16 (pitch 144B)
#define LS_OFF   116736   // logits [64 p][68 k] f32 (pitch 272B)
#define NRM_OFF  134144   // float[256]
#define RINV_OFF 135168   // float[64]
#define SMEM_TOTAL 135424

#define XLd  (XL_OFF - XH_OFF)

__device__ float g_S1p[2][Nn][Kk][Dd];
__device__ float g_S2p[2][Nn][Kk];

static __device__ __forceinline__ uint32_t smem_u32(const void* p) {
    uint32_t a;
    asm("{ .reg .u64 t; cvta.to.shared.u64 t, %1; cvt.u32.u64 %0, t; }" : "=r"(a) : "l"(p));
    return a;
}

static __device__ __forceinline__ void ldsm4(uint32_t r[4], uint32_t a) {
    asm volatile("ldmatrix.sync.aligned.m8n8.x4.shared.b16 {%0,%1,%2,%3}, [%4];"
                 : "=r"(r[0]), "=r"(r[1]), "=r"(r[2]), "=r"(r[3]) : "r"(a));
}
static __device__ __forceinline__ void ldsm4t(uint32_t r[4], uint32_t a) {
    asm volatile("ldmatrix.sync.aligned.m8n8.x4.trans.shared.b16 {%0,%1,%2,%3}, [%4];"
                 : "=r"(r[0]), "=r"(r[1]), "=r"(r[2]), "=r"(r[3]) : "r"(a));
}
static __device__ __forceinline__ void mma_f16(float c[4], const uint32_t a[4],
                                               uint32_t b0, uint32_t b1) {
    asm volatile(
        "mma.sync.aligned.m16n8k16.row.col.f32.f16.f16.f32 "
        "{%0,%1,%2,%3},{%4,%5,%6,%7},{%8,%9},{%0,%1,%2,%3};"
        : "+f"(c[0]), "+f"(c[1]), "+f"(c[2]), "+f"(c[3])
        : "r"(a[0]), "r"(a[1]), "r"(a[2]), "r"(a[3]), "r"(b0), "r"(b1));
}

__global__ void netvlad_noop() {}

__global__ __launch_bounds__(256, 1)
void netvlad_mma(const float* __restrict__ x, const float* __restrict__ w) {
    extern __shared__ char sm[];
    const uint32_t sb = smem_u32(sm);
    const int tid = threadIdx.x;
    const int wid = tid >> 5;
    const int lane = tid & 31;
    const int n  = blockIdx.x >> 1;
    const int hf = blockIdx.x & 1;
    const int p  = tid & 63;
    const int db = tid >> 6;

    float* nrm  = (float*)(sm + NRM_OFF);
    float* rinv = (float*)(sm + RINV_OFF);
    float* Lsp  = (float*)(sm + LS_OFF);

    // ---- load W (fp16 hi only): WH [k][d], pitch 264 halves ----
    for (int i = tid; i < Kk * Dd; i += 256) {
        int k = i >> 8, d = i & 255;
        *(__half*)(sm + WH_OFF + k * 528 + 2 * d) = __float2half_rn(w[i]);
    }

    // GEMM2 accumulators: warp tile [64 d][32 k] -> 4x4 frags x 4 f32
    const int d0 = (wid >> 1) * 64;
    const int kq = (wid & 1) * 32;
    float acc[4][4][4];
#pragma unroll
    for (int i = 0; i < 4; i++)
#pragma unroll
        for (int j = 0; j < 4; j++)
#pragma unroll
            for (int q = 0; q < 4; q++) acc[i][j][q] = 0.0f;
    float s2acc = 0.0f;

    const float* xbase = x + ((size_t)n * Dd + db * 64) * Ll + (size_t)hf * 2048 + p;

    // GEMM1 warp tile: [16 p][32 k]
    const int p0  = (wid >> 1) * 16;
    const int k0w = (wid & 1) * 32;
    const uint32_t aA1 = sb + XH_OFF +
        ((lane & 7) + ((lane >> 4) << 3)) * 144 + (p0 + ((lane >> 3) & 1) * 8) * 2;
    const uint32_t aB1 = sb + WH_OFF + (k0w + (lane & 15)) * 528 + ((lane >> 4) << 4);
    const uint32_t aA2 = sb + XH_OFF + (d0 + (lane & 15)) * 144 + ((lane >> 4) << 4);
    const uint32_t aB2 = sb + PAH_OFF + (kq + (lane & 15)) * 144 + ((lane >> 4) << 4);

    const int g  = lane >> 2;
    const int tg = lane & 3;

    for (int tile = 0; tile < NTILES; ++tile) {
        // ---- 1: load x slice (64 d-values for pixel p), coalesced ----
        const float* src = xbase + tile * 64;
        float xr[64];
#pragma unroll 8
        for (int j = 0; j < 64; ++j) xr[j] = src[(size_t)j * Ll];
        float s = 0.0f;
#pragma unroll
        for (int j = 0; j < 64; ++j) s += xr[j] * xr[j];
        nrm[tid] = s;
        __syncthreads();
        if (tid < 64) {
            float t = nrm[tid] + nrm[64 + tid] + nrm[128 + tid] + nrm[192 + tid];
            rinv[tid] = 1.0f / fmaxf(sqrtf(t), 1e-12f);
        }
        __syncthreads();
        const float ri = rinv[p];

        // ---- 2: convert + store xhat hi/lo [d][p] (fp16 split) ----
#pragma unroll 8
        for (int j = 0; j < 64; ++j) {
            int d = db * 64 + j;
            float v = xr[j] * ri;
            __half hi = __float2half_rn(v);
            __half lo = __float2half_rn(v - __half2float(hi));
            *(__half*)(sm + XH_OFF + d * 144 + 2 * p) = hi;
            *(__half*)(sm + XL_OFF + d * 144 + 2 * p) = lo;
        }
        __syncthreads();

        // ---- 3: GEMM1 logits[p][k] = xhat^T @ W^T (contraction d) ----
        {
            float lacc[4][4];
#pragma unroll
            for (int j = 0; j < 4; j++)
#pragma unroll
                for (int q = 0; q < 4; q++) lacc[j][q] = 0.0f;
#pragma unroll 4
            for (int ks = 0; ks < 16; ++ks) {
                uint32_t Ah[4], Al[4], B0h[4], B1h[4];
                ldsm4t(Ah, aA1 + ks * 2304);
                ldsm4t(Al, aA1 + XLd + ks * 2304);
                ldsm4(B0h, aB1 + ks * 32);
                ldsm4(B1h, aB1 + 16 * 528 + ks * 32);
                mma_f16(lacc[0], Ah, B0h[0], B0h[2]);
                mma_f16(lacc[0], Al, B0h[0], B0h[2]);
                mma_f16(lacc[1], Ah, B0h[1], B0h[3]);
                mma_f16(lacc[1], Al, B0h[1], B0h[3]);
                mma_f16(lacc[2], Ah, B1h[0], B1h[2]);
                mma_f16(lacc[2], Al, B1h[0], B1h[2]);
                mma_f16(lacc[3], Ah, B1h[1], B1h[3]);
                mma_f16(lacc[3], Al, B1h[1], B1h[3]);
            }
#pragma unroll
            for (int j = 0; j < 4; ++j) {
                int kk = k0w + 8 * j + tg * 2;
                *(float2*)&Lsp[(p0 + g) * 68 + kk]     = make_float2(lacc[j][0], lacc[j][1]);
                *(float2*)&Lsp[(p0 + 8 + g) * 68 + kk] = make_float2(lacc[j][2], lacc[j][3]);
            }
        }
        __syncthreads();

        // ---- 4: softmax over k (thread p owns pixel p) ----
        if (tid < 64) {
            const float* row = Lsp + tid * 68;
            float e[64];
            float m = -1e30f;
#pragma unroll 8
            for (int k = 0; k < 64; ++k) { e[k] = row[k]; m = fmaxf(m, e[k]); }
            float ssum = 0.0f;
#pragma unroll 8
            for (int k = 0; k < 64; ++k) { e[k] = __expf(e[k] - m); ssum += e[k]; }
            float inv = 1.0f / ssum;
#pragma unroll 8
            for (int k = 0; k < 64; ++k)
                *(__half*)(sm + PAH_OFF + k * 144 + 2 * tid) = __float2half_rn(e[k] * inv);
        }
        __syncthreads();

        // ---- 5: S2 partials (threads 64..127, k = tid-64) ----
        if (tid >= 64 && tid < 128) {
            int k = tid - 64;
            const __half2* rh = (const __half2*)(sm + PAH_OFF + k * 144);
            float a = 0.0f;
#pragma unroll 8
            for (int c = 0; c < 32; ++c) {
                float2 v = __half22float2(rh[c]);
                a += v.x + v.y;
            }
            s2acc += a;
        }

        // ---- 6: GEMM2 acc[d][k] += xhat @ probs^T (contraction p) ----
#pragma unroll
        for (int ps = 0; ps < 4; ++ps) {
            uint32_t B0h[4], B1h[4];
            ldsm4(B0h, aB2 + ps * 32);
            ldsm4(B1h, aB2 + 16 * 144 + ps * 32);
#pragma unroll
            for (int i = 0; i < 4; ++i) {
                uint32_t Ah[4], Al[4];
                ldsm4(Ah, aA2 + i * 2304 + ps * 32);
                ldsm4(Al, aA2 + XLd + i * 2304 + ps * 32);
                mma_f16(acc[i][0], Ah, B0h[0], B0h[2]);
                mma_f16(acc[i][0], Al, B0h[0], B0h[2]);
                mma_f16(acc[i][1], Ah, B0h[1], B0h[3]);
                mma_f16(acc[i][1], Al, B0h[1], B0h[3]);
                mma_f16(acc[i][2], Ah, B1h[0], B1h[2]);
                mma_f16(acc[i][2], Al, B1h[0], B1h[2]);
                mma_f16(acc[i][3], Ah, B1h[1], B1h[3]);
                mma_f16(acc[i][3], Al, B1h[1], B1h[3]);
            }
        }
        // next tile's first __syncthreads (after nrm store) protects operand reuse
    }

    // ---- flush: transpose via smem (reuse XH region), coalesced global write ----
    __syncthreads();
    float* stg = (float*)(sm + XH_OFF);   // [64 k][260 d] f32
#pragma unroll
    for (int i = 0; i < 4; ++i)
#pragma unroll
        for (int j = 0; j < 4; ++j) {
            int d  = d0 + 16 * i + g;
            int kk = kq + 8 * j + tg * 2;
            stg[kk * 260 + d]           = acc[i][j][0];
            stg[(kk + 1) * 260 + d]     = acc[i][j][1];
            stg[kk * 260 + d + 8]       = acc[i][j][2];
            stg[(kk + 1) * 260 + d + 8] = acc[i][j][3];
        }
    __syncthreads();
    {
        int k  = tid >> 2;
        int dq = (tid & 3) * 64;
#pragma unroll
        for (int jj = 0; jj < 16; ++jj) {
            float4 v = *(float4*)&stg[k * 260 + dq + jj * 4];
            *(float4*)&g_S1p[hf][n][k][dq + jj * 4] = v;
        }
    }
    if (tid >= 64 && tid < 128) g_S2p[hf][n][tid - 64] = s2acc;
}

__global__ __launch_bounds__(256)
void netvlad_finalize(const float* __restrict__ cent, float* __restrict__ out) {
    const int n = blockIdx.x;
    const int tid = threadIdx.x;
    const int w8 = tid >> 5, lane = tid & 31;
    __shared__ float s2s[64];
    __shared__ float wsum[8];
    __shared__ float ginv_s;

    if (tid < 64) s2s[tid] = g_S2p[0][n][tid] + g_S2p[1][n][tid];
    __syncthreads();

    float v[8][8];
    float gs = 0.0f;
#pragma unroll
    for (int kk = 0; kk < 8; ++kk) {
        int k = w8 * 8 + kk;
        float s2 = s2s[k];
        float loc = 0.0f;
#pragma unroll
        for (int j = 0; j < 8; ++j) {
            int d = j * 32 + lane;
            float a = g_S1p[0][n][k][d] + g_S1p[1][n][k][d] - s2 * cent[k * Dd + d];
            v[kk][j] = a;
            loc += a * a;
        }
#pragma unroll
        for (int o = 16; o > 0; o >>= 1) loc += __shfl_xor_sync(0xffffffffu, loc, o);
        float inv = 1.0f / fmaxf(sqrtf(loc), 1e-12f);
#pragma unroll
        for (int j = 0; j < 8; ++j) { v[kk][j] *= inv; gs += v[kk][j] * v[kk][j]; }
    }
#pragma unroll
    for (int o = 16; o > 0; o >>= 1) gs += __shfl_xor_sync(0xffffffffu, gs, o);
    if (lane == 0) wsum[w8] = gs;
    __syncthreads();
    if (tid == 0) {
        float t = 0.0f;
#pragma unroll
        for (int i = 0; i < 8; ++i) t += wsum[i];
        ginv_s = 1.0f / fmaxf(sqrtf(t), 1e-12f);
    }
    __syncthreads();
    float gi = ginv_s;
    size_t base = (size_t)n * Kk * Dd;
#pragma unroll
    for (int kk = 0; kk < 8; ++kk) {
        int k = w8 * 8 + kk;
#pragma unroll
        for (int j = 0; j < 8; ++j)
            out[base + (size_t)k * Dd + j * 32 + lane] = v[kk][j] * gi;
    }
}

extern "C" void kernel_launch(void* const* d_in, const int* in_sizes, int n_in,
                              void* d_out, int out_size) {
    const float* x = (const float*)d_in[0];
    const float* w = (const float*)d_in[1];
    const float* c = (const float*)d_in[2];
    float* out = (float*)d_out;

    cudaFuncSetAttribute(netvlad_mma,
                         cudaFuncAttributeMaxDynamicSharedMemorySize, SMEM_TOTAL);

    // 3-launch pattern: ncu (-s 5 -c 1, with 2 harness launches preceding)
    // captures my launch #4 == netvlad_mma on the second replay.
    netvlad_mma<<<2 * Nn, 256, SMEM_TOTAL>>>(x, w);
    netvlad_finalize<<<Nn, 256>>>(c, out);
    netvlad_noop<<<1, 32>>>();
}

// round 8
// speedup vs baseline: 2.3255x; 1.3121x over previous
#include <cuda_runtime.h>
#include <cuda_fp16.h>
#include <cstdint>
#include <math.h>

#define Nn 64
#define Kk 64
#define Dd 256
#define Ll 4096
#define NTILES 32
#define NT 512

// ---- smem layout (bytes); pitches % 128 == 16 for conflict-free ldmatrix ----
#define XH_OFF   0        // xhat hi  [256 d][72 p] f16 (pitch 144B)
#define XL_OFF   36864    // xhat lo
#define WH_OFF   73728    // W hi [64 k][264 d] f16 (pitch 528B)
#define PAH_OFF  107520   // probs hi [64 k][72 p] f16 (pitch 144B)
#define LS_OFF   116736   // logits [64 p][68 k] f32 (pitch 272B)
#define NRM_OFF  134144   // float[512]
#define RINV_OFF 136192   // float[64]
#define SMEM_TOTAL 136448

#define XLd  (XL_OFF - XH_OFF)

__device__ float g_S1p[2][Nn][Kk][Dd];
__device__ float g_S2p[2][Nn][Kk];

static __device__ __forceinline__ uint32_t smem_u32(const void* p) {
    uint32_t a;
    asm("{ .reg .u64 t; cvta.to.shared.u64 t, %1; cvt.u32.u64 %0, t; }" : "=r"(a) : "l"(p));
    return a;
}
static __device__ __forceinline__ void ldsm4(uint32_t r[4], uint32_t a) {
    asm volatile("ldmatrix.sync.aligned.m8n8.x4.shared.b16 {%0,%1,%2,%3}, [%4];"
                 : "=r"(r[0]), "=r"(r[1]), "=r"(r[2]), "=r"(r[3]) : "r"(a));
}
static __device__ __forceinline__ void ldsm4t(uint32_t r[4], uint32_t a) {
    asm volatile("ldmatrix.sync.aligned.m8n8.x4.trans.shared.b16 {%0,%1,%2,%3}, [%4];"
                 : "=r"(r[0]), "=r"(r[1]), "=r"(r[2]), "=r"(r[3]) : "r"(a));
}
static __device__ __forceinline__ void mma_f16(float c[4], const uint32_t a[4],
                                               uint32_t b0, uint32_t b1) {
    asm volatile(
        "mma.sync.aligned.m16n8k16.row.col.f32.f16.f16.f32 "
        "{%0,%1,%2,%3},{%4,%5,%6,%7},{%8,%9},{%0,%1,%2,%3};"
        : "+f"(c[0]), "+f"(c[1]), "+f"(c[2]), "+f"(c[3])
        : "r"(a[0]), "r"(a[1]), "r"(a[2]), "r"(a[3]), "r"(b0), "r"(b1));
}

__global__ void netvlad_noop() {}

__global__ __launch_bounds__(NT, 1)
void netvlad_mma(const float* __restrict__ x, const float* __restrict__ w) {
    extern __shared__ char sm[];
    const uint32_t sb = smem_u32(sm);
    const int tid = threadIdx.x;
    const int wid = tid >> 5;
    const int lane = tid & 31;
    const int n  = blockIdx.x >> 1;
    const int hf = blockIdx.x & 1;
    const int p  = tid & 63;
    const int db = tid >> 6;       // 0..7, owns d-range db*32..+31

    float* nrm  = (float*)(sm + NRM_OFF);
    float* rinv = (float*)(sm + RINV_OFF);
    float* Lsp  = (float*)(sm + LS_OFF);

    // ---- load W (fp16): WH [k][d], pitch 264 halves ----
    for (int i = tid; i < Kk * Dd; i += NT) {
        int k = i >> 8, d = i & 255;
        *(__half*)(sm + WH_OFF + k * 528 + 2 * d) = __float2half_rn(w[i]);
    }

    // GEMM2 warp tile [32 d][32 k]: 16 warps = 8 d-groups x 2 k-groups
    const int d0 = (wid >> 1) * 32;
    const int kq = (wid & 1) * 32;
    float acc[2][4][4];
#pragma unroll
    for (int i = 0; i < 2; i++)
#pragma unroll
        for (int j = 0; j < 4; j++)
#pragma unroll
            for (int q = 0; q < 4; q++) acc[i][j][q] = 0.0f;
    float s2acc = 0.0f;

    const float* xbase = x + ((size_t)n * Dd + db * 32) * Ll + (size_t)hf * 2048 + p;

    // GEMM1 warp tile [16 p][16 k]: p0 = (wid>>2)*16, k0 = (wid&3)*16
    const int p0  = (wid >> 2) * 16;
    const int k0w = (wid & 3) * 16;
    const uint32_t aA1 = sb + XH_OFF +
        ((lane & 7) + ((lane >> 4) << 3)) * 144 + (p0 + ((lane >> 3) & 1) * 8) * 2;
    const uint32_t aB1 = sb + WH_OFF + (k0w + (lane & 15)) * 528 + ((lane >> 4) << 4);
    const uint32_t aA2 = sb + XH_OFF + (d0 + (lane & 15)) * 144 + ((lane >> 4) << 4);
    const uint32_t aB2 = sb + PAH_OFF + (kq + (lane & 15)) * 144 + ((lane >> 4) << 4);

    const int g  = lane >> 2;
    const int tg = lane & 3;

    // ---- prefetch tile 0 ----
    float xr[32];
#pragma unroll 8
    for (int j = 0; j < 32; ++j) xr[j] = xbase[(size_t)j * Ll];

    for (int tile = 0; tile < NTILES; ++tile) {
        // ---- 1: norms from prefetched xr ----
        float s = 0.0f;
#pragma unroll
        for (int j = 0; j < 32; ++j) s += xr[j] * xr[j];
        nrm[tid] = s;
        __syncthreads();
        if (tid < 64) {
            float t = 0.0f;
#pragma unroll
            for (int i = 0; i < 8; ++i) t += nrm[tid + 64 * i];
            rinv[tid] = 1.0f / fmaxf(sqrtf(t), 1e-12f);
        }
        __syncthreads();
        const float ri = rinv[p];

        // ---- 2: convert + store xhat hi/lo [d][p], then prefetch next tile ----
#pragma unroll 8
        for (int j = 0; j < 32; ++j) {
            int d = db * 32 + j;
            float v = xr[j] * ri;
            __half hi = __float2half_rn(v);
            __half lo = __float2half_rn(v - __half2float(hi));
            *(__half*)(sm + XH_OFF + d * 144 + 2 * p) = hi;
            *(__half*)(sm + XL_OFF + d * 144 + 2 * p) = lo;
        }
        if (tile + 1 < NTILES) {
            const float* src = xbase + (tile + 1) * 64;
#pragma unroll 8
            for (int j = 0; j < 32; ++j) xr[j] = src[(size_t)j * Ll];
        }
        __syncthreads();

        // ---- 3: GEMM1 logits[p][k] (contraction d=256) ----
        {
            float lh0[4] = {0, 0, 0, 0}, lh1[4] = {0, 0, 0, 0};
            float ll0[4] = {0, 0, 0, 0}, ll1[4] = {0, 0, 0, 0};
#pragma unroll 4
            for (int ks = 0; ks < 16; ++ks) {
                uint32_t Ah[4], Al[4], B[4];
                ldsm4t(Ah, aA1 + ks * 2304);
                ldsm4t(Al, aA1 + XLd + ks * 2304);
                ldsm4(B, aB1 + ks * 32);
                mma_f16(lh0, Ah, B[0], B[2]);
                mma_f16(lh1, Ah, B[1], B[3]);
                mma_f16(ll0, Al, B[0], B[2]);
                mma_f16(ll1, Al, B[1], B[3]);
            }
#pragma unroll
            for (int q = 0; q < 4; ++q) { lh0[q] += ll0[q]; lh1[q] += ll1[q]; }
            int kk0 = k0w + tg * 2, kk1 = k0w + 8 + tg * 2;
            *(float2*)&Lsp[(p0 + g) * 68 + kk0]     = make_float2(lh0[0], lh0[1]);
            *(float2*)&Lsp[(p0 + 8 + g) * 68 + kk0] = make_float2(lh0[2], lh0[3]);
            *(float2*)&Lsp[(p0 + g) * 68 + kk1]     = make_float2(lh1[0], lh1[1]);
            *(float2*)&Lsp[(p0 + 8 + g) * 68 + kk1] = make_float2(lh1[2], lh1[3]);
        }
        __syncthreads();

        // ---- 4: softmax over k (thread p owns pixel p) ----
        if (tid < 64) {
            const float* row = Lsp + tid * 68;
            float e[64];
            float m = -1e30f;
#pragma unroll 8
            for (int k = 0; k < 64; ++k) { e[k] = row[k]; m = fmaxf(m, e[k]); }
            float ssum = 0.0f;
#pragma unroll 8
            for (int k = 0; k < 64; ++k) { e[k] = __expf(e[k] - m); ssum += e[k]; }
            float inv = 1.0f / ssum;
#pragma unroll 8
            for (int k = 0; k < 64; ++k)
                *(__half*)(sm + PAH_OFF + k * 144 + 2 * tid) = __float2half_rn(e[k] * inv);
        }
        __syncthreads();

        // ---- 5: S2 partials (threads 64..127, k = tid-64) ----
        if (tid >= 64 && tid < 128) {
            int k = tid - 64;
            const __half2* rh = (const __half2*)(sm + PAH_OFF + k * 144);
            float a = 0.0f;
#pragma unroll 8
            for (int c = 0; c < 32; ++c) {
                float2 v = __half22float2(rh[c]);
                a += v.x + v.y;
            }
            s2acc += a;
        }

        // ---- 6: GEMM2 acc[d][k] += xhat @ probs^T (contraction p=64) ----
#pragma unroll
        for (int ps = 0; ps < 4; ++ps) {
            uint32_t B0[4], B1[4];
            ldsm4(B0, aB2 + ps * 32);
            ldsm4(B1, aB2 + 16 * 144 + ps * 32);
#pragma unroll
            for (int i = 0; i < 2; ++i) {
                uint32_t Ah[4], Al[4];
                ldsm4(Ah, aA2 + i * 2304 + ps * 32);
                ldsm4(Al, aA2 + XLd + i * 2304 + ps * 32);
                mma_f16(acc[i][0], Ah, B0[0], B0[2]);
                mma_f16(acc[i][1], Ah, B0[1], B0[3]);
                mma_f16(acc[i][2], Ah, B1[0], B1[2]);
                mma_f16(acc[i][3], Ah, B1[1], B1[3]);
                mma_f16(acc[i][0], Al, B0[0], B0[2]);
                mma_f16(acc[i][1], Al, B0[1], B0[3]);
                mma_f16(acc[i][2], Al, B1[0], B1[2]);
                mma_f16(acc[i][3], Al, B1[1], B1[3]);
            }
        }
        // next tile's first __syncthreads protects operand buffer reuse
    }

    // ---- flush: transpose via smem (reuse XH+XL region), coalesced write ----
    __syncthreads();
    float* stg = (float*)(sm + XH_OFF);   // [64 k][260 d] f32 (66.6KB < 73.7KB)
#pragma unroll
    for (int i = 0; i < 2; ++i)
#pragma unroll
        for (int j = 0; j < 4; ++j) {
            int d  = d0 + 16 * i + g;
            int kk = kq + 8 * j + tg * 2;
            stg[kk * 260 + d]           = acc[i][j][0];
            stg[(kk + 1) * 260 + d]     = acc[i][j][1];
            stg[kk * 260 + d + 8]       = acc[i][j][2];
            stg[(kk + 1) * 260 + d + 8] = acc[i][j][3];
        }
    __syncthreads();
    {
        int k  = tid >> 3;
        int dq = (tid & 7) * 32;
#pragma unroll
        for (int jj = 0; jj < 8; ++jj) {
            float4 v = *(float4*)&stg[k * 260 + dq + jj * 4];
            *(float4*)&g_S1p[hf][n][k][dq + jj * 4] = v;
        }
    }
    if (tid >= 64 && tid < 128) g_S2p[hf][n][tid - 64] = s2acc;
}

__global__ __launch_bounds__(256)
void netvlad_finalize(const float* __restrict__ cent, float* __restrict__ out) {
    const int n = blockIdx.x;
    const int tid = threadIdx.x;
    const int w8 = tid >> 5, lane = tid & 31;
    __shared__ float s2s[64];
    __shared__ float wsum[8];
    __shared__ float ginv_s;

    if (tid < 64) s2s[tid] = g_S2p[0][n][tid] + g_S2p[1][n][tid];
    __syncthreads();

    float v[8][8];
    float gs = 0.0f;
#pragma unroll
    for (int kk = 0; kk < 8; ++kk) {
        int k = w8 * 8 + kk;
        float s2 = s2s[k];
        float loc = 0.0f;
#pragma unroll
        for (int j = 0; j < 8; ++j) {
            int d = j * 32 + lane;
            float a = g_S1p[0][n][k][d] + g_S1p[1][n][k][d] - s2 * cent[k * Dd + d];
            v[kk][j] = a;
            loc += a * a;
        }
#pragma unroll
        for (int o = 16; o > 0; o >>= 1) loc += __shfl_xor_sync(0xffffffffu, loc, o);
        float inv = 1.0f / fmaxf(sqrtf(loc), 1e-12f);
#pragma unroll
        for (int j = 0; j < 8; ++j) { v[kk][j] *= inv; gs += v[kk][j] * v[kk][j]; }
    }
#pragma unroll
    for (int o = 16; o > 0; o >>= 1) gs += __shfl_xor_sync(0xffffffffu, gs, o);
    if (lane == 0) wsum[w8] = gs;
    __syncthreads();
    if (tid == 0) {
        float t = 0.0f;
#pragma unroll
        for (int i = 0; i < 8; ++i) t += wsum[i];
        ginv_s = 1.0f / fmaxf(sqrtf(t), 1e-12f);
    }
    __syncthreads();
    float gi = ginv_s;
    size_t base = (size_t)n * Kk * Dd;
#pragma unroll
    for (int kk = 0; kk < 8; ++kk) {
        int k = w8 * 8 + kk;
#pragma unroll
        for (int j = 0; j < 8; ++j)
            out[base + (size_t)k * Dd + j * 32 + lane] = v[kk][j] * gi;
    }
}

extern "C" void kernel_launch(void* const* d_in, const int* in_sizes, int n_in,
                              void* d_out, int out_size) {
    const float* x = (const float*)d_in[0];
    const float* w = (const float*)d_in[1];
    const float* c = (const float*)d_in[2];
    float* out = (float*)d_out;

    cudaFuncSetAttribute(netvlad_mma,
                         cudaFuncAttributeMaxDynamicSharedMemorySize, SMEM_TOTAL);

    // 3-launch pattern keeps ncu (-s 5 -c 1) on netvlad_mma.
    netvlad_mma<<<2 * Nn, NT, SMEM_TOTAL>>>(x, w);
    netvlad_finalize<<<Nn, 256>>>(c, out);
    netvlad_noop<<<1, 32>>>();
}

// round 9
// speedup vs baseline: 3.1892x; 1.3714x over previous
#include <cuda_runtime.h>
#include <cuda_fp16.h>
#include <cstdint>
#include <math.h>

#define Nn 64
#define Kk 64
#define Dd 256
#define Ll 4096
#define NTILES 32
#define NT 512

// ---- smem layout (bytes); pitches % 128 == 16 for conflict-free ldmatrix ----
#define XH_OFF   0        // xhat [256 d][72 p] f16 (pitch 144B)
#define WH_OFF   36864    // W [64 k][264 d] f16 (pitch 528B)
#define PAH_OFF  70656    // probs [64 k][72 p] f16 (pitch 144B)
#define LS_OFF   79872    // logits [64 p][68 k] f32 (pitch 272B)
#define NRM_OFF  97280    // float[512]
#define RINV_OFF 99328    // float[64]
#define SMEM_TOTAL 99584

__device__ float g_S1p[2][Nn][Kk][Dd];
__device__ float g_S2p[2][Nn][Kk];

static __device__ __forceinline__ uint32_t smem_u32(const void* p) {
    uint32_t a;
    asm("{ .reg .u64 t; cvta.to.shared.u64 t, %1; cvt.u32.u64 %0, t; }" : "=r"(a) : "l"(p));
    return a;
}
static __device__ __forceinline__ void ldsm4(uint32_t r[4], uint32_t a) {
    asm volatile("ldmatrix.sync.aligned.m8n8.x4.shared.b16 {%0,%1,%2,%3}, [%4];"
                 : "=r"(r[0]), "=r"(r[1]), "=r"(r[2]), "=r"(r[3]) : "r"(a));
}
static __device__ __forceinline__ void ldsm4t(uint32_t r[4], uint32_t a) {
    asm volatile("ldmatrix.sync.aligned.m8n8.x4.trans.shared.b16 {%0,%1,%2,%3}, [%4];"
                 : "=r"(r[0]), "=r"(r[1]), "=r"(r[2]), "=r"(r[3]) : "r"(a));
}
static __device__ __forceinline__ void mma_f16(float c[4], const uint32_t a[4],
                                               uint32_t b0, uint32_t b1) {
    asm volatile(
        "mma.sync.aligned.m16n8k16.row.col.f32.f16.f16.f32 "
        "{%0,%1,%2,%3},{%4,%5,%6,%7},{%8,%9},{%0,%1,%2,%3};"
        : "+f"(c[0]), "+f"(c[1]), "+f"(c[2]), "+f"(c[3])
        : "r"(a[0]), "r"(a[1]), "r"(a[2]), "r"(a[3]), "r"(b0), "r"(b1));
}

__global__ void netvlad_noop() {}

__global__ __launch_bounds__(NT, 1)
void netvlad_mma(const float* __restrict__ x, const float* __restrict__ w) {
    extern __shared__ char sm[];
    const uint32_t sb = smem_u32(sm);
    const int tid = threadIdx.x;
    const int wid = tid >> 5;
    const int lane = tid & 31;
    const int n  = blockIdx.x >> 1;
    const int hf = blockIdx.x & 1;
    const int p  = tid & 63;
    const int db = tid >> 6;       // 0..7, owns d-range db*32..+31

    float* nrm  = (float*)(sm + NRM_OFF);
    float* rinv = (float*)(sm + RINV_OFF);
    float* Lsp  = (float*)(sm + LS_OFF);

    // ---- load W (fp16): WH [k][d], pitch 264 halves ----
    for (int i = tid; i < Kk * Dd; i += NT) {
        int k = i >> 8, d = i & 255;
        *(__half*)(sm + WH_OFF + k * 528 + 2 * d) = __float2half_rn(w[i]);
    }

    // GEMM2 warp tile [32 d][32 k]: 16 warps = 8 d-groups x 2 k-groups
    const int d0 = (wid >> 1) * 32;
    const int kq = (wid & 1) * 32;
    float acc[2][4][4];
#pragma unroll
    for (int i = 0; i < 2; i++)
#pragma unroll
        for (int j = 0; j < 4; j++)
#pragma unroll
            for (int q = 0; q < 4; q++) acc[i][j][q] = 0.0f;
    float s2acc = 0.0f;

    const float* xbase = x + ((size_t)n * Dd + db * 32) * Ll + (size_t)hf * 2048 + p;

    // GEMM1 warp tile [16 p][16 k]
    const int p0  = (wid >> 2) * 16;
    const int k0w = (wid & 3) * 16;
    const uint32_t aA1 = sb + XH_OFF +
        ((lane & 7) + ((lane >> 4) << 3)) * 144 + (p0 + ((lane >> 3) & 1) * 8) * 2;
    const uint32_t aB1 = sb + WH_OFF + (k0w + (lane & 15)) * 528 + ((lane >> 4) << 4);
    const uint32_t aA2 = sb + XH_OFF + (d0 + (lane & 15)) * 144 + ((lane >> 4) << 4);
    const uint32_t aB2 = sb + PAH_OFF + (kq + (lane & 15)) * 144 + ((lane >> 4) << 4);

    const int g  = lane >> 2;
    const int tg = lane & 3;

    // softmax/S2 group decomposition: 8 threads per pixel / per cluster
    const int sp  = tid >> 3;      // pixel (softmax) / cluster k (S2)
    const int sg  = tid & 7;       // subgroup index

    // ---- prefetch tile 0 ----
    float xr[32];
#pragma unroll 8
    for (int j = 0; j < 32; ++j) xr[j] = xbase[(size_t)j * Ll];

    for (int tile = 0; tile < NTILES; ++tile) {
        // ---- 1: norms from prefetched xr ----
        float s = 0.0f;
#pragma unroll
        for (int j = 0; j < 32; ++j) s += xr[j] * xr[j];
        nrm[tid] = s;
        __syncthreads();
        if (tid < 64) {
            float t = 0.0f;
#pragma unroll
            for (int i = 0; i < 8; ++i) t += nrm[tid + 64 * i];
            rinv[tid] = 1.0f / fmaxf(sqrtf(t), 1e-12f);
        }
        __syncthreads();
        const float ri = rinv[p];

        // ---- 2: convert + store xhat [d][p] fp16, then prefetch next tile ----
#pragma unroll 8
        for (int j = 0; j < 32; ++j) {
            int d = db * 32 + j;
            *(__half*)(sm + XH_OFF + d * 144 + 2 * p) = __float2half_rn(xr[j] * ri);
        }
        if (tile + 1 < NTILES) {
            const float* src = xbase + (tile + 1) * 64;
#pragma unroll 8
            for (int j = 0; j < 32; ++j) xr[j] = src[(size_t)j * Ll];
        }
        __syncthreads();

        // ---- 3: GEMM1 logits[p][k] (contraction d=256) ----
        {
            float lh0[4] = {0, 0, 0, 0}, lh1[4] = {0, 0, 0, 0};
#pragma unroll 4
            for (int ks = 0; ks < 16; ++ks) {
                uint32_t Ah[4], B[4];
                ldsm4t(Ah, aA1 + ks * 2304);
                ldsm4(B, aB1 + ks * 32);
                mma_f16(lh0, Ah, B[0], B[2]);
                mma_f16(lh1, Ah, B[1], B[3]);
            }
            int kk0 = k0w + tg * 2, kk1 = k0w + 8 + tg * 2;
            *(float2*)&Lsp[(p0 + g) * 68 + kk0]     = make_float2(lh0[0], lh0[1]);
            *(float2*)&Lsp[(p0 + 8 + g) * 68 + kk0] = make_float2(lh0[2], lh0[3]);
            *(float2*)&Lsp[(p0 + g) * 68 + kk1]     = make_float2(lh1[0], lh1[1]);
            *(float2*)&Lsp[(p0 + 8 + g) * 68 + kk1] = make_float2(lh1[2], lh1[3]);
        }
        __syncthreads();

        // ---- 4: softmax over k, 8 threads per pixel ----
        {
            float e[8];
            const float* row = Lsp + sp * 68 + sg * 8;
            float4 v0 = *(const float4*)row;
            float4 v1 = *(const float4*)(row + 4);
            e[0] = v0.x; e[1] = v0.y; e[2] = v0.z; e[3] = v0.w;
            e[4] = v1.x; e[5] = v1.y; e[6] = v1.z; e[7] = v1.w;
            float m = e[0];
#pragma unroll
            for (int j = 1; j < 8; ++j) m = fmaxf(m, e[j]);
#pragma unroll
            for (int o = 1; o < 8; o <<= 1) m = fmaxf(m, __shfl_xor_sync(0xffffffffu, m, o));
            float ssum = 0.0f;
#pragma unroll
            for (int j = 0; j < 8; ++j) { e[j] = __expf(e[j] - m); ssum += e[j]; }
#pragma unroll
            for (int o = 1; o < 8; o <<= 1) ssum += __shfl_xor_sync(0xffffffffu, ssum, o);
            float inv = 1.0f / ssum;
#pragma unroll
            for (int j = 0; j < 8; ++j)
                *(__half*)(sm + PAH_OFF + (sg * 8 + j) * 144 + 2 * sp) =
                    __float2half_rn(e[j] * inv);
        }
        __syncthreads();

        // ---- 5: S2 partials, 8 threads per cluster (k = sp) ----
        {
            const __half2* rh = (const __half2*)(sm + PAH_OFF + sp * 144 + sg * 16);
            float a = 0.0f;
#pragma unroll
            for (int c = 0; c < 4; ++c) {
                float2 v = __half22float2(rh[c]);
                a += v.x + v.y;
            }
#pragma unroll
            for (int o = 1; o < 8; o <<= 1) a += __shfl_xor_sync(0xffffffffu, a, o);
            if (sg == 0) s2acc += a;
        }

        // ---- 6: GEMM2 acc[d][k] += xhat @ probs^T (contraction p=64) ----
#pragma unroll
        for (int ps = 0; ps < 4; ++ps) {
            uint32_t B0[4], B1[4];
            ldsm4(B0, aB2 + ps * 32);
            ldsm4(B1, aB2 + 16 * 144 + ps * 32);
#pragma unroll
            for (int i = 0; i < 2; ++i) {
                uint32_t Ah[4];
                ldsm4(Ah, aA2 + i * 2304 + ps * 32);
                mma_f16(acc[i][0], Ah, B0[0], B0[2]);
                mma_f16(acc[i][1], Ah, B0[1], B0[3]);
                mma_f16(acc[i][2], Ah, B1[0], B1[2]);
                mma_f16(acc[i][3], Ah, B1[1], B1[3]);
            }
        }
        // next tile's first __syncthreads protects operand buffer reuse
    }

    // ---- flush: transpose via smem (reuse XH/WH region), coalesced write ----
    __syncthreads();
    float* stg = (float*)(sm + XH_OFF);   // [64 k][260 d] f32 = 66560B < 70656B
#pragma unroll
    for (int i = 0; i < 2; ++i)
#pragma unroll
        for (int j = 0; j < 4; ++j) {
            int d  = d0 + 16 * i + g;
            int kk = kq + 8 * j + tg * 2;
            stg[kk * 260 + d]           = acc[i][j][0];
            stg[(kk + 1) * 260 + d]     = acc[i][j][1];
            stg[kk * 260 + d + 8]       = acc[i][j][2];
            stg[(kk + 1) * 260 + d + 8] = acc[i][j][3];
        }
    __syncthreads();
    {
        int k  = tid >> 3;
        int dq = (tid & 7) * 32;
#pragma unroll
        for (int jj = 0; jj < 8; ++jj) {
            float4 v = *(float4*)&stg[k * 260 + dq + jj * 4];
            *(float4*)&g_S1p[hf][n][k][dq + jj * 4] = v;
        }
    }
    if ((tid & 7) == 0) g_S2p[hf][n][tid >> 3] = s2acc;
}

__global__ __launch_bounds__(256)
void netvlad_finalize(const float* __restrict__ cent, float* __restrict__ out) {
    const int n = blockIdx.x;
    const int tid = threadIdx.x;
    const int w8 = tid >> 5, lane = tid & 31;
    __shared__ float s2s[64];
    __shared__ float wsum[8];
    __shared__ float ginv_s;

    if (tid < 64) s2s[tid] = g_S2p[0][n][tid] + g_S2p[1][n][tid];
    __syncthreads();

    float v[8][8];
    float gs = 0.0f;
#pragma unroll
    for (int kk = 0; kk < 8; ++kk) {
        int k = w8 * 8 + kk;
        float s2 = s2s[k];
        float loc = 0.0f;
#pragma unroll
        for (int j = 0; j < 8; ++j) {
            int d = j * 32 + lane;
            float a = g_S1p[0][n][k][d] + g_S1p[1][n][k][d] - s2 * cent[k * Dd + d];
            v[kk][j] = a;
            loc += a * a;
        }
#pragma unroll
        for (int o = 16; o > 0; o >>= 1) loc += __shfl_xor_sync(0xffffffffu, loc, o);
        float inv = 1.0f / fmaxf(sqrtf(loc), 1e-12f);
#pragma unroll
        for (int j = 0; j < 8; ++j) { v[kk][j] *= inv; gs += v[kk][j] * v[kk][j]; }
    }
#pragma unroll
    for (int o = 16; o > 0; o >>= 1) gs += __shfl_xor_sync(0xffffffffu, gs, o);
    if (lane == 0) wsum[w8] = gs;
    __syncthreads();
    if (tid == 0) {
        float t = 0.0f;
#pragma unroll
        for (int i = 0; i < 8; ++i) t += wsum[i];
        ginv_s = 1.0f / fmaxf(sqrtf(t), 1e-12f);
    }
    __syncthreads();
    float gi = ginv_s;
    size_t base = (size_t)n * Kk * Dd;
#pragma unroll
    for (int kk = 0; kk < 8; ++kk) {
        int k = w8 * 8 + kk;
#pragma unroll
        for (int j = 0; j < 8; ++j)
            out[base + (size_t)k * Dd + j * 32 + lane] = v[kk][j] * gi;
    }
}

extern "C" void kernel_launch(void* const* d_in, const int* in_sizes, int n_in,
                              void* d_out, int out_size) {
    const float* x = (const float*)d_in[0];
    const float* w = (const float*)d_in[1];
    const float* c = (const float*)d_in[2];
    float* out = (float*)d_out;

    cudaFuncSetAttribute(netvlad_mma,
                         cudaFuncAttributeMaxDynamicSharedMemorySize, SMEM_TOTAL);

    // 3-launch pattern keeps ncu (-s 5 -c 1) on netvlad_mma.
    netvlad_mma<<<2 * Nn, NT, SMEM_TOTAL>>>(x, w);
    netvlad_finalize<<<Nn, 256>>>(c, out);
    netvlad_noop<<<1, 32>>>();
}

// round 10
// speedup vs baseline: 4.9634x; 1.5563x over previous
#include <cuda_runtime.h>
#include <cuda_fp16.h>
#include <cstdint>
#include <math.h>

#define Nn 64
#define Kk 64
#define Dd 256
#define Ll 4096
#define NTILES 32
#define NT 512

// ---- smem byte offsets ----
#define XRAW_OFF 0        // raw x fp32 [256 d][68 p] (pitch 272B)
#define XH0_OFF  69632    // x fp16 [256 d][72 p] (pitch 144B), parity 0
#define XH1_OFF  106496   // parity 1
#define WH_OFF   143360   // W fp16 [64 k][264 d] (pitch 528B)
#define PA0_OFF  177152   // probs*ri fp16 [64 k][72 p] (pitch 144B), parity 0
#define PA1_OFF  186368   // parity 1
#define LS_OFF   195584   // logits [64 p][68 k] f32 (pitch 272B)
#define NRM_OFF  212992   // float[256] partial sumsq
#define RN_OFF   214016   // float[2][64]  ri = 1/||x||
#define NX_OFF   214528   // float[2][64]  ||x||
#define SMEM_TOTAL 215040

#define XHD (XH1_OFF - XH0_OFF)   // 36864
#define PAD (PA1_OFF - PA0_OFF)   // 9216

__device__ float g_S1p[2][Nn][Kk][Dd];
__device__ float g_S2p[2][Nn][Kk];

static __device__ __forceinline__ uint32_t smem_u32(const void* p) {
    uint32_t a;
    asm("{ .reg .u64 t; cvta.to.shared.u64 t, %1; cvt.u32.u64 %0, t; }" : "=r"(a) : "l"(p));
    return a;
}
static __device__ __forceinline__ void ldsm4(uint32_t r[4], uint32_t a) {
    asm volatile("ldmatrix.sync.aligned.m8n8.x4.shared.b16 {%0,%1,%2,%3}, [%4];"
                 : "=r"(r[0]), "=r"(r[1]), "=r"(r[2]), "=r"(r[3]) : "r"(a));
}
static __device__ __forceinline__ void ldsm4t(uint32_t r[4], uint32_t a) {
    asm volatile("ldmatrix.sync.aligned.m8n8.x4.trans.shared.b16 {%0,%1,%2,%3}, [%4];"
                 : "=r"(r[0]), "=r"(r[1]), "=r"(r[2]), "=r"(r[3]) : "r"(a));
}
static __device__ __forceinline__ void mma_f16(float c[4], const uint32_t a[4],
                                               uint32_t b0, uint32_t b1) {
    asm volatile(
        "mma.sync.aligned.m16n8k16.row.col.f32.f16.f16.f32 "
        "{%0,%1,%2,%3},{%4,%5,%6,%7},{%8,%9},{%0,%1,%2,%3};"
        : "+f"(c[0]), "+f"(c[1]), "+f"(c[2]), "+f"(c[3])
        : "r"(a[0]), "r"(a[1]), "r"(a[2]), "r"(a[3]), "r"(b0), "r"(b1));
}
#define BAR_SYNC(id, cnt)   asm volatile("bar.sync %0, %1;"   :: "r"(id), "r"(cnt) : "memory")
#define BAR_ARRIVE(id, cnt) asm volatile("bar.arrive %0, %1;" :: "r"(id), "r"(cnt) : "memory")
#define CP_ASYNC16(dst, src) \
    asm volatile("cp.async.cg.shared.global [%0], [%1], 16;" :: "r"(dst), "l"(src) : "memory")
#define CP_COMMIT()  asm volatile("cp.async.commit_group;" ::: "memory")
#define CP_WAIT0()   asm volatile("cp.async.wait_group 0;" ::: "memory")

__global__ void netvlad_noop() {}

__global__ __launch_bounds__(NT, 1)
void netvlad_mma(const float* __restrict__ x, const float* __restrict__ w) {
    extern __shared__ char sm[];
    const uint32_t sb = smem_u32(sm);
    const int tid = threadIdx.x;
    const int lane = tid & 31;
    const int n  = blockIdx.x >> 1;
    const int hf = blockIdx.x & 1;

    float* nrm = (float*)(sm + NRM_OFF);
    float* Lsp = (float*)(sm + LS_OFF);
    float* RN  = (float*)(sm + RN_OFF);
    float* NX  = (float*)(sm + NX_OFF);

    // ---- load W fp16 [k][d] pitch 264 halves (all 512 threads) ----
    for (int i = tid; i < Kk * Dd; i += NT) {
        int k = i >> 8, d = i & 255;
        *(__half*)(sm + WH_OFF + k * 528 + 2 * d) = __float2half_rn(w[i]);
    }

    const float* xn = x + (size_t)n * Dd * Ll + (size_t)hf * 2048;

    // ---- G1 issues cp.async for tile 0 ----
    if (tid < 256) {
#pragma unroll 4
        for (int i = 0; i < 16; ++i) {
            int c = tid + 256 * i;
            int d = c >> 4, p4 = c & 15;
            uint32_t dst = sb + XRAW_OFF + d * 272 + p4 * 16;
            const float* src = xn + (size_t)d * Ll + p4 * 4;
            CP_ASYNC16(dst, src);
        }
        CP_COMMIT();
    }
    __syncthreads();

    if (tid < 256) {
        // ================= G1: load/convert/GEMM1/softmax =================
        const int p  = tid & 63;
        const int dq = tid >> 6;       // 0..3
        const int wv = tid >> 5;       // 0..7
        const int p0 = (wv >> 1) * 16;
        const int k0 = (wv & 1) * 32;
        const int g  = lane >> 2;
        const int tg = lane & 3;
        const int pp = tid >> 2;       // softmax pixel
        const int sg = tid & 3;        // softmax subgroup

        const uint32_t aA1b = sb + XH0_OFF +
            ((lane & 7) + ((lane >> 4) << 3)) * 144 + (p0 + ((lane >> 3) & 1) * 8) * 2;
        const uint32_t aB1 = sb + WH_OFF + (k0 + (lane & 15)) * 528 + ((lane >> 4) << 4);

        for (int t = 0; t < NTILES; ++t) {
            const int par = t & 1;
            const uint32_t xh_off = par ? XH1_OFF : XH0_OFF;

            CP_WAIT0();
            if (t >= 2) { BAR_SYNC(2 + par, NT); } else { BAR_SYNC(1, 256); }

            // convert raw x -> fp16 XH[par], accumulate sumsq
            {
                const float* col = (const float*)(sm + XRAW_OFF) + (dq * 64) * 68 + p;
                char* dstc = sm + xh_off + (dq * 64) * 144 + 2 * p;
                float s = 0.0f;
#pragma unroll 8
                for (int j = 0; j < 64; ++j) {
                    float v = col[j * 68];
                    s += v * v;
                    *(__half*)(dstc + j * 144) = __float2half_rn(v);
                }
                nrm[tid] = s;
            }
            BAR_SYNC(1, 256);

            // prefetch next tile into XRAW (everyone done reading it)
            if (t + 1 < NTILES) {
#pragma unroll 4
                for (int i = 0; i < 16; ++i) {
                    int c = tid + 256 * i;
                    int d = c >> 4, p4 = c & 15;
                    uint32_t dst = sb + XRAW_OFF + d * 272 + p4 * 16;
                    const float* src = xn + (size_t)d * Ll + (t + 1) * 64 + p4 * 4;
                    CP_ASYNC16(dst, src);
                }
                CP_COMMIT();
            }
            if (tid < 64) {
                float q = nrm[tid] + nrm[tid + 64] + nrm[tid + 128] + nrm[tid + 192];
                float nx = fmaxf(sqrtf(q), 1e-12f);
                NX[par * 64 + tid] = nx;
                RN[par * 64 + tid] = 1.0f / nx;
            }
            BAR_SYNC(1, 256);

            // GEMM1: logits_raw[p][k] = x^T W^T  (contraction d=256)
            {
                float l0[4] = {0, 0, 0, 0}, l1[4] = {0, 0, 0, 0};
                float l2[4] = {0, 0, 0, 0}, l3[4] = {0, 0, 0, 0};
                const uint32_t a1 = aA1b + (par ? XHD : 0);
#pragma unroll 4
                for (int ks = 0; ks < 16; ++ks) {
                    uint32_t A[4], B0[4], B1[4];
                    ldsm4t(A, a1 + ks * 2304);
                    ldsm4(B0, aB1 + ks * 32);
                    ldsm4(B1, aB1 + 16 * 528 + ks * 32);
                    mma_f16(l0, A, B0[0], B0[2]);
                    mma_f16(l1, A, B0[1], B0[3]);
                    mma_f16(l2, A, B1[0], B1[2]);
                    mma_f16(l3, A, B1[1], B1[3]);
                }
                int r0 = (p0 + g) * 68, r1 = (p0 + 8 + g) * 68;
                *(float2*)&Lsp[r0 + k0 + tg * 2]      = make_float2(l0[0], l0[1]);
                *(float2*)&Lsp[r1 + k0 + tg * 2]      = make_float2(l0[2], l0[3]);
                *(float2*)&Lsp[r0 + k0 + 8 + tg * 2]  = make_float2(l1[0], l1[1]);
                *(float2*)&Lsp[r1 + k0 + 8 + tg * 2]  = make_float2(l1[2], l1[3]);
                *(float2*)&Lsp[r0 + k0 + 16 + tg * 2] = make_float2(l2[0], l2[1]);
                *(float2*)&Lsp[r1 + k0 + 16 + tg * 2] = make_float2(l2[2], l2[3]);
                *(float2*)&Lsp[r0 + k0 + 24 + tg * 2] = make_float2(l3[0], l3[1]);
                *(float2*)&Lsp[r1 + k0 + 24 + tg * 2] = make_float2(l3[2], l3[3]);
            }
            BAR_SYNC(1, 256);

            // softmax over k (4 threads per pixel), write probs*ri fp16
            {
                const float ri = RN[par * 64 + pp];
                const float* row = Lsp + pp * 68 + sg * 16;
                float e[16];
                float4 v0 = *(const float4*)(row + 0);
                float4 v1 = *(const float4*)(row + 4);
                float4 v2 = *(const float4*)(row + 8);
                float4 v3 = *(const float4*)(row + 12);
                e[0]=v0.x; e[1]=v0.y; e[2]=v0.z; e[3]=v0.w;
                e[4]=v1.x; e[5]=v1.y; e[6]=v1.z; e[7]=v1.w;
                e[8]=v2.x; e[9]=v2.y; e[10]=v2.z; e[11]=v2.w;
                e[12]=v3.x; e[13]=v3.y; e[14]=v3.z; e[15]=v3.w;
                float m = e[0];
#pragma unroll
                for (int j = 1; j < 16; ++j) m = fmaxf(m, e[j]);
                m = fmaxf(m, __shfl_xor_sync(0xffffffffu, m, 1));
                m = fmaxf(m, __shfl_xor_sync(0xffffffffu, m, 2));
                float ssum = 0.0f;
#pragma unroll
                for (int j = 0; j < 16; ++j) { e[j] = __expf(ri * (e[j] - m)); ssum += e[j]; }
                ssum += __shfl_xor_sync(0xffffffffu, ssum, 1);
                ssum += __shfl_xor_sync(0xffffffffu, ssum, 2);
                float sc = ri / ssum;
                char* pd = sm + (par ? PA1_OFF : PA0_OFF) + (sg * 16) * 144 + 2 * pp;
#pragma unroll
                for (int j = 0; j < 16; ++j)
                    *(__half*)(pd + j * 144) = __float2half_rn(e[j] * sc);
            }
            BAR_ARRIVE(4 + par, NT);
        }
    } else {
        // ================= G2: GEMM2 + S2 =================
        const int t2 = tid - 256;
        const int w2 = t2 >> 5;
        const int d0 = (w2 >> 1) * 64;
        const int kq = (w2 & 1) * 32;
        const int g  = lane >> 2;
        const int tg = lane & 3;
        const int sk = t2 >> 2;        // S2 cluster
        const int s4 = t2 & 3;

        const uint32_t aA2b = sb + XH0_OFF + (d0 + (lane & 15)) * 144 + ((lane >> 4) << 4);
        const uint32_t aB2b = sb + PA0_OFF + (kq + (lane & 15)) * 144 + ((lane >> 4) << 4);

        float acc[4][4][4];
#pragma unroll
        for (int i = 0; i < 4; i++)
#pragma unroll
            for (int j = 0; j < 4; j++)
#pragma unroll
                for (int q = 0; q < 4; q++) acc[i][j][q] = 0.0f;
        float s2acc = 0.0f;

        for (int t = 0; t < NTILES; ++t) {
            const int par = t & 1;
            BAR_SYNC(4 + par, NT);

            const uint32_t a2 = aA2b + (par ? XHD : 0);
            const uint32_t b2 = aB2b + (par ? PAD : 0);
#pragma unroll
            for (int ps = 0; ps < 4; ++ps) {
                uint32_t B0[4], B1[4];
                ldsm4(B0, b2 + ps * 32);
                ldsm4(B1, b2 + 16 * 144 + ps * 32);
#pragma unroll
                for (int i = 0; i < 4; ++i) {
                    uint32_t A[4];
                    ldsm4(A, a2 + i * 2304 + ps * 32);
                    mma_f16(acc[i][0], A, B0[0], B0[2]);
                    mma_f16(acc[i][1], A, B0[1], B0[3]);
                    mma_f16(acc[i][2], A, B1[0], B1[2]);
                    mma_f16(acc[i][3], A, B1[1], B1[3]);
                }
            }
            // S2[k] += sum_p probs*ri * ||x||  (4 threads per k)
            {
                const __half2* rh = (const __half2*)(sm + (par ? PA1_OFF : PA0_OFF)
                                                     + sk * 144 + s4 * 32);
                const float* nx = (float*)(sm + NX_OFF) + par * 64 + s4 * 16;
                float a = 0.0f;
#pragma unroll
                for (int c = 0; c < 8; ++c) {
                    float2 v = __half22float2(rh[c]);
                    a += v.x * nx[2 * c] + v.y * nx[2 * c + 1];
                }
                a += __shfl_xor_sync(0xffffffffu, a, 1);
                a += __shfl_xor_sync(0xffffffffu, a, 2);
                if (s4 == 0) s2acc += a;
            }
            BAR_ARRIVE(2 + par, NT);
        }

        if (s4 == 0) g_S2p[hf][n][sk] = s2acc;

        // stage acc into smem for coalesced global write (after barrier below)
        __syncthreads();   // joins G1 (all 512)
        float* stg = (float*)sm;   // [64 k][260 d] f32 in XRAW region
#pragma unroll
        for (int i = 0; i < 4; ++i)
#pragma unroll
            for (int j = 0; j < 4; ++j) {
                int d  = d0 + 16 * i + g;
                int kk = kq + 8 * j + tg * 2;
                stg[kk * 260 + d]           = acc[i][j][0];
                stg[(kk + 1) * 260 + d]     = acc[i][j][1];
                stg[kk * 260 + d + 8]       = acc[i][j][2];
                stg[(kk + 1) * 260 + d + 8] = acc[i][j][3];
            }
    }

    if (tid < 256) __syncthreads();   // G1 joins the staging barrier
    __syncthreads();                  // staging complete
    {
        int k  = tid >> 3;
        int dq2 = (tid & 7) * 32;
        const float* stg = (const float*)sm;
#pragma unroll
        for (int jj = 0; jj < 8; ++jj) {
            float4 v = *(const float4*)&stg[k * 260 + dq2 + jj * 4];
            *(float4*)&g_S1p[hf][n][k][dq2 + jj * 4] = v;
        }
    }
}

__global__ __launch_bounds__(256)
void netvlad_finalize(const float* __restrict__ cent, float* __restrict__ out) {
    const int n = blockIdx.x;
    const int tid = threadIdx.x;
    const int w8 = tid >> 5, lane = tid & 31;
    __shared__ float s2s[64];
    __shared__ float wsum[8];
    __shared__ float ginv_s;

    if (tid < 64) s2s[tid] = g_S2p[0][n][tid] + g_S2p[1][n][tid];
    __syncthreads();

    float v[8][8];
    float gs = 0.0f;
#pragma unroll
    for (int kk = 0; kk < 8; ++kk) {
        int k = w8 * 8 + kk;
        float s2 = s2s[k];
        float loc = 0.0f;
#pragma unroll
        for (int j = 0; j < 8; ++j) {
            int d = j * 32 + lane;
            float a = g_S1p[0][n][k][d] + g_S1p[1][n][k][d] - s2 * cent[k * Dd + d];
            v[kk][j] = a;
            loc += a * a;
        }
#pragma unroll
        for (int o = 16; o > 0; o >>= 1) loc += __shfl_xor_sync(0xffffffffu, loc, o);
        float inv = 1.0f / fmaxf(sqrtf(loc), 1e-12f);
#pragma unroll
        for (int j = 0; j < 8; ++j) { v[kk][j] *= inv; gs += v[kk][j] * v[kk][j]; }
    }
#pragma unroll
    for (int o = 16; o > 0; o >>= 1) gs += __shfl_xor_sync(0xffffffffu, gs, o);
    if (lane == 0) wsum[w8] = gs;
    __syncthreads();
    if (tid == 0) {
        float t = 0.0f;
#pragma unroll
        for (int i = 0; i < 8; ++i) t += wsum[i];
        ginv_s = 1.0f / fmaxf(sqrtf(t), 1e-12f);
    }
    __syncthreads();
    float gi = ginv_s;
    size_t base = (size_t)n * Kk * Dd;
#pragma unroll
    for (int kk = 0; kk < 8; ++kk) {
        int k = w8 * 8 + kk;
#pragma unroll
        for (int j = 0; j < 8; ++j)
            out[base + (size_t)k * Dd + j * 32 + lane] = v[kk][j] * gi;
    }
}

extern "C" void kernel_launch(void* const* d_in, const int* in_sizes, int n_in,
                              void* d_out, int out_size) {
    const float* x = (const float*)d_in[0];
    const float* w = (const float*)d_in[1];
    const float* c = (const float*)d_in[2];
    float* out = (float*)d_out;

    cudaFuncSetAttribute(netvlad_mma,
                         cudaFuncAttributeMaxDynamicSharedMemorySize, SMEM_TOTAL);

    // 3-launch pattern keeps ncu (-s 5 -c 1) on netvlad_mma.
    netvlad_mma<<<2 * Nn, NT, SMEM_TOTAL>>>(x, w);
    netvlad_finalize<<<Nn, 256>>>(c, out);
    netvlad_noop<<<1, 32>>>();
}

// round 12
// speedup vs baseline: 5.8125x; 1.1711x over previous
#include <cuda_runtime.h>
#include <cuda_fp16.h>
#include <cstdint>
#include <math.h>

#define Nn 64
#define Kk 64
#define Dd 256
#define Ll 4096
#define NTILES 32
#define NT 512

// ---- smem byte offsets ----
#define XRAW_OFF 0        // raw x fp32 [256 d][68 p] (pitch 272B)
#define XH0_OFF  69632    // x fp16 [256 d][72 p] (pitch 144B), parity 0
#define XH1_OFF  106496   // parity 1
#define WH_OFF   143360   // W fp16 [64 k][264 d] (pitch 528B)
#define PA0_OFF  177152   // probs*ri fp16 [64 k][72 p] (pitch 144B), parity 0
#define PA1_OFF  186368   // parity 1
#define LS_OFF   195584   // logits [64 p][68 k] f32 (pitch 272B)
#define NRM_OFF  212992   // float[2][512] partial sumsq (parity stride 512)
#define RN_OFF   217088   // float[2][64]  ri = 1/||x||
#define NX_OFF   217600   // float[2][64]  ||x||
#define SMEM_TOTAL 218112

#define XHD (XH1_OFF - XH0_OFF)   // 36864
#define PAD (PA1_OFF - PA0_OFF)   // 9216

__device__ float g_S1p[2][Nn][Kk][Dd];
__device__ float g_S2p[2][Nn][Kk];

static __device__ __forceinline__ uint32_t smem_u32(const void* p) {
    uint32_t a;
    asm("{ .reg .u64 t; cvta.to.shared.u64 t, %1; cvt.u32.u64 %0, t; }" : "=r"(a) : "l"(p));
    return a;
}
static __device__ __forceinline__ void ldsm4(uint32_t r[4], uint32_t a) {
    asm volatile("ldmatrix.sync.aligned.m8n8.x4.shared.b16 {%0,%1,%2,%3}, [%4];"
                 : "=r"(r[0]), "=r"(r[1]), "=r"(r[2]), "=r"(r[3]) : "r"(a));
}
static __device__ __forceinline__ void ldsm4t(uint32_t r[4], uint32_t a) {
    asm volatile("ldmatrix.sync.aligned.m8n8.x4.trans.shared.b16 {%0,%1,%2,%3}, [%4];"
                 : "=r"(r[0]), "=r"(r[1]), "=r"(r[2]), "=r"(r[3]) : "r"(a));
}
static __device__ __forceinline__ void mma_f16(float c[4], const uint32_t a[4],
                                               uint32_t b0, uint32_t b1) {
    asm volatile(
        "mma.sync.aligned.m16n8k16.row.col.f32.f16.f16.f32 "
        "{%0,%1,%2,%3},{%4,%5,%6,%7},{%8,%9},{%0,%1,%2,%3};"
        : "+f"(c[0]), "+f"(c[1]), "+f"(c[2]), "+f"(c[3])
        : "r"(a[0]), "r"(a[1]), "r"(a[2]), "r"(a[3]), "r"(b0), "r"(b1));
}
#define BAR_SYNC(id, cnt)   asm volatile("bar.sync %0, %1;"   :: "r"(id), "r"(cnt) : "memory")
#define BAR_ARRIVE(id, cnt) asm volatile("bar.arrive %0, %1;" :: "r"(id), "r"(cnt) : "memory")
#define CP_ASYNC16(dst, src) \
    asm volatile("cp.async.cg.shared.global [%0], [%1], 16;" :: "r"(dst), "l"(src) : "memory")
#define CP_COMMIT()  asm volatile("cp.async.commit_group;" ::: "memory")
#define CP_WAIT0()   asm volatile("cp.async.wait_group 0;" ::: "memory")

// named barrier ids:
// 1 = G1 internal, 7 = G2 internal
// 2/3 = XHfree par0/1 (G1 arrives post-GEMM1, G2 syncs pre-convert)
// 4/5 = XHready par0/1 (G2 arrives post-convert, G1 syncs pre-GEMM1)
// 8/9 = PAready par0/1 (G1 arrives post-softmax, G2 syncs pre-GEMM2)

__global__ void netvlad_noop() {}

__global__ __launch_bounds__(NT, 1)
void netvlad_mma(const float* __restrict__ x, const float* __restrict__ w) {
    extern __shared__ char sm[];
    const uint32_t sb = smem_u32(sm);
    const int tid = threadIdx.x;
    const int lane = tid & 31;
    const int n  = blockIdx.x >> 1;
    const int hf = blockIdx.x & 1;

    float* Lsp = (float*)(sm + LS_OFF);
    float* RN  = (float*)(sm + RN_OFF);
    float* NX  = (float*)(sm + NX_OFF);

    // ---- load W fp16 [k][d] pitch 264 halves (all 512 threads) ----
    for (int i = tid; i < Kk * Dd; i += NT) {
        int k = i >> 8, d = i & 255;
        *(__half*)(sm + WH_OFF + k * 528 + 2 * d) = __float2half_rn(w[i]);
    }

    const float* xn = x + (size_t)n * Dd * Ll + (size_t)hf * 2048;

    // ---- G2 issues cp.async for tile 0 ----
    if (tid >= 256) {
        const int t2 = tid - 256;
#pragma unroll 4
        for (int i = 0; i < 16; ++i) {
            int c = t2 + 256 * i;
            int d = c >> 4, p4 = c & 15;
            uint32_t dst = sb + XRAW_OFF + d * 272 + p4 * 16;
            const float* src = xn + (size_t)d * Ll + p4 * 4;
            CP_ASYNC16(dst, src);
        }
        CP_COMMIT();
    }
    __syncthreads();

    if (tid < 256) {
        // ============ G1: norm-reduce + GEMM1 + softmax ============
        const int wv = tid >> 5;
        const int p0 = (wv >> 1) * 16;
        const int k0 = (wv & 1) * 32;
        const int g  = lane >> 2;
        const int tg = lane & 3;
        const int pp = tid >> 2;       // softmax pixel
        const int sg = tid & 3;        // softmax subgroup

        const uint32_t aA1b = sb + XH0_OFF +
            ((lane & 7) + ((lane >> 4) << 3)) * 144 + (p0 + ((lane >> 3) & 1) * 8) * 2;
        const uint32_t aB1 = sb + WH_OFF + (k0 + (lane & 15)) * 528 + ((lane >> 4) << 4);

        for (int t = 0; t < NTILES; ++t) {
            const int par = t & 1;
            BAR_SYNC(4 + par, NT);          // XH[par] + nrm[par] ready

            // norm reduction (warps 0,1): 512 partials per parity
            if (tid < 64) {
                const float* nr = (const float*)(sm + NRM_OFF) + par * 512;
                float q = 0.0f;
#pragma unroll
                for (int i = 0; i < 8; ++i) q += nr[i * 64 + tid];
                float nx = fmaxf(sqrtf(q), 1e-12f);
                NX[par * 64 + tid] = nx;
                RN[par * 64 + tid] = 1.0f / nx;
            }

            // GEMM1: logits_raw[p][k] = x^T W^T  (contraction d=256)
            {
                float l0[4] = {0, 0, 0, 0}, l1[4] = {0, 0, 0, 0};
                float l2[4] = {0, 0, 0, 0}, l3[4] = {0, 0, 0, 0};
                const uint32_t a1 = aA1b + (par ? XHD : 0);
#pragma unroll 4
                for (int ks = 0; ks < 16; ++ks) {
                    uint32_t A[4], B0[4], B1[4];
                    ldsm4t(A, a1 + ks * 2304);
                    ldsm4(B0, aB1 + ks * 32);
                    ldsm4(B1, aB1 + 16 * 528 + ks * 32);
                    mma_f16(l0, A, B0[0], B0[2]);
                    mma_f16(l1, A, B0[1], B0[3]);
                    mma_f16(l2, A, B1[0], B1[2]);
                    mma_f16(l3, A, B1[1], B1[3]);
                }
                int r0 = (p0 + g) * 68, r1 = (p0 + 8 + g) * 68;
                *(float2*)&Lsp[r0 + k0 + tg * 2]      = make_float2(l0[0], l0[1]);
                *(float2*)&Lsp[r1 + k0 + tg * 2]      = make_float2(l0[2], l0[3]);
                *(float2*)&Lsp[r0 + k0 + 8 + tg * 2]  = make_float2(l1[0], l1[1]);
                *(float2*)&Lsp[r1 + k0 + 8 + tg * 2]  = make_float2(l1[2], l1[3]);
                *(float2*)&Lsp[r0 + k0 + 16 + tg * 2] = make_float2(l2[0], l2[1]);
                *(float2*)&Lsp[r1 + k0 + 16 + tg * 2] = make_float2(l2[2], l2[3]);
                *(float2*)&Lsp[r0 + k0 + 24 + tg * 2] = make_float2(l3[0], l3[1]);
                *(float2*)&Lsp[r1 + k0 + 24 + tg * 2] = make_float2(l3[2], l3[3]);
            }
            BAR_ARRIVE(2 + par, NT);        // XH[par] reads done -> G2 may overwrite
            BAR_SYNC(1, 256);               // logits + RN visible within G1

            // softmax over k (4 threads per pixel), write probs*ri fp16
            {
                const float ri = RN[par * 64 + pp];
                const float* row = Lsp + pp * 68 + sg * 16;
                float e[16];
                float4 v0 = *(const float4*)(row + 0);
                float4 v1 = *(const float4*)(row + 4);
                float4 v2 = *(const float4*)(row + 8);
                float4 v3 = *(const float4*)(row + 12);
                e[0]=v0.x; e[1]=v0.y; e[2]=v0.z; e[3]=v0.w;
                e[4]=v1.x; e[5]=v1.y; e[6]=v1.z; e[7]=v1.w;
                e[8]=v2.x; e[9]=v2.y; e[10]=v2.z; e[11]=v2.w;
                e[12]=v3.x; e[13]=v3.y; e[14]=v3.z; e[15]=v3.w;
                float m = e[0];
#pragma unroll
                for (int j = 1; j < 16; ++j) m = fmaxf(m, e[j]);
                m = fmaxf(m, __shfl_xor_sync(0xffffffffu, m, 1));
                m = fmaxf(m, __shfl_xor_sync(0xffffffffu, m, 2));
                float ssum = 0.0f;
#pragma unroll
                for (int j = 0; j < 16; ++j) { e[j] = __expf(ri * (e[j] - m)); ssum += e[j]; }
                ssum += __shfl_xor_sync(0xffffffffu, ssum, 1);
                ssum += __shfl_xor_sync(0xffffffffu, ssum, 2);
                float sc = ri / ssum;
                char* pd = sm + (par ? PA1_OFF : PA0_OFF) + (sg * 16) * 144 + 2 * pp;
#pragma unroll
                for (int j = 0; j < 16; ++j)
                    *(__half*)(pd + j * 144) = __float2half_rn(e[j] * sc);
            }
            BAR_ARRIVE(8 + par, NT);        // PA[par] ready
            BAR_SYNC(1, 256);               // LS reads done before next GEMM1
        }
    } else {
        // ============ G2: convert + cp.async + GEMM2 + S2 ============
        const int t2 = tid - 256;
        const int pq = t2 & 31;        // pixel pair: p = 2pq, 2pq+1
        const int dq = t2 >> 5;        // 0..7, d-range dq*32..+31
        const int d0 = (dq >> 1) * 64;
        const int kq = (dq & 1) * 32;
        const int g  = lane >> 2;
        const int tg = lane & 3;
        const int sk = t2 >> 2;        // S2 cluster
        const int s4 = t2 & 3;

        const uint32_t aA2b = sb + XH0_OFF + (d0 + (lane & 15)) * 144 + ((lane >> 4) << 4);
        const uint32_t aB2b = sb + PA0_OFF + (kq + (lane & 15)) * 144 + ((lane >> 4) << 4);

        float acc[4][4][4];
#pragma unroll
        for (int i = 0; i < 4; i++)
#pragma unroll
            for (int j = 0; j < 4; j++)
#pragma unroll
                for (int q = 0; q < 4; q++) acc[i][j][q] = 0.0f;
        float s2acc = 0.0f;

        for (int t = 0; t < NTILES; ++t) {
            const int par = t & 1;
            if (t >= 2) BAR_SYNC(2 + par, NT);   // XH[par] free (G1 GEMM1 t-2 done)
            CP_WAIT0();

            // convert XRAW -> fp16 XH[par], sumsq partials (2 pixels/thread)
            {
                const char* srcb = sm + XRAW_OFF + 8 * pq;
                char* dstb = sm + (par ? XH1_OFF : XH0_OFF) + 4 * pq;
                float s0 = 0.0f, s1 = 0.0f;
#pragma unroll 8
                for (int j = 0; j < 32; ++j) {
                    int d = dq * 32 + j;
                    float2 v = *(const float2*)(srcb + d * 272);
                    s0 += v.x * v.x;
                    s1 += v.y * v.y;
                    *(__half2*)(dstb + d * 144) = __floats2half2_rn(v.x, v.y);
                }
                // partial layout: float index dq*64 + 2*pq (+1); 512 floats/parity
                float2* nr2 = (float2*)((float*)(sm + NRM_OFF) + par * 512);
                nr2[dq * 32 + pq] = make_float2(s0, s1);
            }
            BAR_SYNC(7, 256);                    // all XRAW reads done

            if (t + 1 < NTILES) {
#pragma unroll 4
                for (int i = 0; i < 16; ++i) {
                    int c = t2 + 256 * i;
                    int d = c >> 4, p4 = c & 15;
                    uint32_t dst = sb + XRAW_OFF + d * 272 + p4 * 16;
                    const float* src = xn + (size_t)d * Ll + (t + 1) * 64 + p4 * 4;
                    CP_ASYNC16(dst, src);
                }
                CP_COMMIT();
            }
            BAR_ARRIVE(4 + par, NT);             // XH[par] + nrm[par] ready

            if (t > 0) {
                const int q = par ^ 1;
                BAR_SYNC(8 + q, NT);             // PA[q] ready
                const uint32_t a2 = aA2b + (q ? XHD : 0);
                const uint32_t b2 = aB2b + (q ? PAD : 0);
#pragma unroll
                for (int ps = 0; ps < 4; ++ps) {
                    uint32_t B0[4], B1[4];
                    ldsm4(B0, b2 + ps * 32);
                    ldsm4(B1, b2 + 16 * 144 + ps * 32);
#pragma unroll
                    for (int i = 0; i < 4; ++i) {
                        uint32_t A[4];
                        ldsm4(A, a2 + i * 2304 + ps * 32);
                        mma_f16(acc[i][0], A, B0[0], B0[2]);
                        mma_f16(acc[i][1], A, B0[1], B0[3]);
                        mma_f16(acc[i][2], A, B1[0], B1[2]);
                        mma_f16(acc[i][3], A, B1[1], B1[3]);
                    }
                }
                // S2[k] += sum_p (probs*ri) * ||x||
                {
                    const __half2* rh = (const __half2*)(sm + (q ? PA1_OFF : PA0_OFF)
                                                         + sk * 144 + s4 * 32);
                    const float* nx = (const float*)(sm + NX_OFF) + q * 64 + s4 * 16;
                    float a = 0.0f;
#pragma unroll
                    for (int c = 0; c < 8; ++c) {
                        float2 v = __half22float2(rh[c]);
                        a += v.x * nx[2 * c] + v.y * nx[2 * c + 1];
                    }
                    a += __shfl_xor_sync(0xffffffffu, a, 1);
                    a += __shfl_xor_sync(0xffffffffu, a, 2);
                    if (s4 == 0) s2acc += a;
                }
            }
        }

        // tail: GEMM2 + S2 for tile 31 (par 1)
        {
            BAR_SYNC(9, NT);
            const uint32_t a2 = aA2b + XHD;
            const uint32_t b2 = aB2b + PAD;
#pragma unroll
            for (int ps = 0; ps < 4; ++ps) {
                uint32_t B0[4], B1[4];
                ldsm4(B0, b2 + ps * 32);
                ldsm4(B1, b2 + 16 * 144 + ps * 32);
#pragma unroll
                for (int i = 0; i < 4; ++i) {
                    uint32_t A[4];
                    ldsm4(A, a2 + i * 2304 + ps * 32);
                    mma_f16(acc[i][0], A, B0[0], B0[2]);
                    mma_f16(acc[i][1], A, B0[1], B0[3]);
                    mma_f16(acc[i][2], A, B1[0], B1[2]);
                    mma_f16(acc[i][3], A, B1[1], B1[3]);
                }
            }
            {
                const __half2* rh = (const __half2*)(sm + PA1_OFF + sk * 144 + s4 * 32);
                const float* nx = (const float*)(sm + NX_OFF) + 64 + s4 * 16;
                float a = 0.0f;
#pragma unroll
                for (int c = 0; c < 8; ++c) {
                    float2 v = __half22float2(rh[c]);
                    a += v.x * nx[2 * c] + v.y * nx[2 * c + 1];
                }
                a += __shfl_xor_sync(0xffffffffu, a, 1);
                a += __shfl_xor_sync(0xffffffffu, a, 2);
                if (s4 == 0) s2acc += a;
            }
        }
        if (s4 == 0) g_S2p[hf][n][sk] = s2acc;

        // stage acc into XRAW region (only G2 touches XRAW; no barrier needed)
        float* stg = (float*)sm;   // [64 k][260 d] f32
#pragma unroll
        for (int i = 0; i < 4; ++i)
#pragma unroll
            for (int j = 0; j < 4; ++j) {
                int d  = d0 + 16 * i + g;
                int kk = kq + 8 * j + tg * 2;
                stg[kk * 260 + d]           = acc[i][j][0];
                stg[(kk + 1) * 260 + d]     = acc[i][j][1];
                stg[kk * 260 + d + 8]       = acc[i][j][2];
                stg[(kk + 1) * 260 + d + 8] = acc[i][j][3];
            }
    }

    __syncthreads();   // staging complete; all 512 threads write S1
    {
        int k   = tid >> 3;
        int dq2 = (tid & 7) * 32;
        const float* stg = (const float*)sm;
#pragma unroll
        for (int jj = 0; jj < 8; ++jj) {
            float4 v = *(const float4*)&stg[k * 260 + dq2 + jj * 4];
            *(float4*)&g_S1p[hf][n][k][dq2 + jj * 4] = v;
        }
    }
}

__global__ __launch_bounds__(256)
void netvlad_finalize(const float* __restrict__ cent, float* __restrict__ out) {
    const int n = blockIdx.x;
    const int tid = threadIdx.x;
    const int w8 = tid >> 5, lane = tid & 31;
    __shared__ float s2s[64];
    __shared__ float wsum[8];
    __shared__ float ginv_s;

    if (tid < 64) s2s[tid] = g_S2p[0][n][tid] + g_S2p[1][n][tid];
    __syncthreads();

    float v[8][8];
    float gs = 0.0f;
#pragma unroll
    for (int kk = 0; kk < 8; ++kk) {
        int k = w8 * 8 + kk;
        float s2 = s2s[k];
        float loc = 0.0f;
#pragma unroll
        for (int j = 0; j < 8; ++j) {
            int d = j * 32 + lane;
            float a = g_S1p[0][n][k][d] + g_S1p[1][n][k][d] - s2 * cent[k * Dd + d];
            v[kk][j] = a;
            loc += a * a;
        }
#pragma unroll
        for (int o = 16; o > 0; o >>= 1) loc += __shfl_xor_sync(0xffffffffu, loc, o);
        float inv = 1.0f / fmaxf(sqrtf(loc), 1e-12f);
#pragma unroll
        for (int j = 0; j < 8; ++j) { v[kk][j] *= inv; gs += v[kk][j] * v[kk][j]; }
    }
#pragma unroll
    for (int o = 16; o > 0; o >>= 1) gs += __shfl_xor_sync(0xffffffffu, gs, o);
    if (lane == 0) wsum[w8] = gs;
    __syncthreads();
    if (tid == 0) {
        float t = 0.0f;
#pragma unroll
        for (int i = 0; i < 8; ++i) t += wsum[i];
        ginv_s = 1.0f / fmaxf(sqrtf(t), 1e-12f);
    }
    __syncthreads();
    float gi = ginv_s;
    size_t base = (size_t)n * Kk * Dd;
#pragma unroll
    for (int kk = 0; kk < 8; ++kk) {
        int k = w8 * 8 + kk;
#pragma unroll
        for (int j = 0; j < 8; ++j)
            out[base + (size_t)k * Dd + j * 32 + lane] = v[kk][j] * gi;
    }
}

extern "C" void kernel_launch(void* const* d_in, const int* in_sizes, int n_in,
                              void* d_out, int out_size) {
    const float* x = (const float*)d_in[0];
    const float* w = (const float*)d_in[1];
    const float* c = (const float*)d_in[2];
    float* out = (float*)d_out;

    cudaFuncSetAttribute(netvlad_mma,
                         cudaFuncAttributeMaxDynamicSharedMemorySize, SMEM_TOTAL);

    // 3-launch pattern keeps ncu (-s 5 -c 1) on netvlad_mma.
    netvlad_mma<<<2 * Nn, NT, SMEM_TOTAL>>>(x, w);
    netvlad_finalize<<<Nn, 256>>>(c, out);
    netvlad_noop<<<1, 32>>>();
}

// round 13
// speedup vs baseline: 6.4769x; 1.1143x over previous
#include <cuda_runtime.h>
#include <cuda_fp16.h>
#include <cstdint>
#include <math.h>

#define Nn 64
#define Kk 64
#define Dd 256
#define Ll 4096
#define NTILES 32
#define NT 512

// ---- smem byte offsets ----
#define XRAW_OFF 0        // raw x fp32 [256 d][68 p] (pitch 272B)
#define XH0_OFF  69632    // x fp16 [256 d][72 p] (pitch 144B), parity 0
#define XH1_OFF  106496   // parity 1
#define WH_OFF   143360   // W fp16 [64 k][264 d] (pitch 528B)
#define PA0_OFF  177152   // probs*ri fp16 [64 p][72 k] (pitch 144B), parity 0
#define PA1_OFF  186368   // parity 1
#define LS_OFF   195584   // logits [64 p][68 k] f32 (pitch 272B)
#define NRM_OFF  212992   // float[2][1024] partial sumsq (parity stride 1024)
#define RN_OFF   221184   // float[2][64]  ri = 1/||x||
#define NX_OFF   221696   // float[2][64]  ||x||
#define SMEM_TOTAL 222208

#define XHD (XH1_OFF - XH0_OFF)   // 36864
#define PAD (PA1_OFF - PA0_OFF)   // 9216

__device__ float g_S1p[2][Nn][Kk][Dd];
__device__ float g_S2p[2][Nn][Kk];

static __device__ __forceinline__ uint32_t smem_u32(const void* p) {
    uint32_t a;
    asm("{ .reg .u64 t; cvta.to.shared.u64 t, %1; cvt.u32.u64 %0, t; }" : "=r"(a) : "l"(p));
    return a;
}
static __device__ __forceinline__ void ldsm4(uint32_t r[4], uint32_t a) {
    asm volatile("ldmatrix.sync.aligned.m8n8.x4.shared.b16 {%0,%1,%2,%3}, [%4];"
                 : "=r"(r[0]), "=r"(r[1]), "=r"(r[2]), "=r"(r[3]) : "r"(a));
}
static __device__ __forceinline__ void ldsm4t(uint32_t r[4], uint32_t a) {
    asm volatile("ldmatrix.sync.aligned.m8n8.x4.trans.shared.b16 {%0,%1,%2,%3}, [%4];"
                 : "=r"(r[0]), "=r"(r[1]), "=r"(r[2]), "=r"(r[3]) : "r"(a));
}
static __device__ __forceinline__ void mma_f16(float c[4], const uint32_t a[4],
                                               uint32_t b0, uint32_t b1) {
    asm volatile(
        "mma.sync.aligned.m16n8k16.row.col.f32.f16.f16.f32 "
        "{%0,%1,%2,%3},{%4,%5,%6,%7},{%8,%9},{%0,%1,%2,%3};"
        : "+f"(c[0]), "+f"(c[1]), "+f"(c[2]), "+f"(c[3])
        : "r"(a[0]), "r"(a[1]), "r"(a[2]), "r"(a[3]), "r"(b0), "r"(b1));
}
#define BAR_SYNC(id, cnt)   asm volatile("bar.sync %0, %1;"   :: "r"(id), "r"(cnt) : "memory")
#define BAR_ARRIVE(id, cnt) asm volatile("bar.arrive %0, %1;" :: "r"(id), "r"(cnt) : "memory")
#define CP_ASYNC16(dst, src) \
    asm volatile("cp.async.cg.shared.global [%0], [%1], 16;" :: "r"(dst), "l"(src) : "memory")
#define CP_COMMIT()  asm volatile("cp.async.commit_group;" ::: "memory")
#define CP_WAIT0()   asm volatile("cp.async.wait_group 0;" ::: "memory")

// named barrier ids:
// 1 = G1 internal, 7 = G2 internal
// 2/3 = XHfree par0/1, 4/5 = XHready par0/1, 8/9 = PAready par0/1

__global__ void netvlad_noop() {}

__global__ __launch_bounds__(NT, 1)
void netvlad_mma(const float* __restrict__ x, const float* __restrict__ w) {
    extern __shared__ char sm[];
    const uint32_t sb = smem_u32(sm);
    const int tid = threadIdx.x;
    const int lane = tid & 31;
    const int n  = blockIdx.x >> 1;
    const int hf = blockIdx.x & 1;

    float* Lsp = (float*)(sm + LS_OFF);
    float* RN  = (float*)(sm + RN_OFF);

    // ---- load W fp16 [k][d] pitch 264 halves (all 512 threads) ----
    for (int i = tid; i < Kk * Dd; i += NT) {
        int k = i >> 8, d = i & 255;
        *(__half*)(sm + WH_OFF + k * 528 + 2 * d) = __float2half_rn(w[i]);
    }

    const float* xn = x + (size_t)n * Dd * Ll + (size_t)hf * 2048;

    // ---- G2 issues cp.async for tile 0 ----
    if (tid >= 256) {
        const int t2 = tid - 256;
#pragma unroll 4
        for (int i = 0; i < 16; ++i) {
            int c = t2 + 256 * i;
            int d = c >> 4, p4 = c & 15;
            uint32_t dst = sb + XRAW_OFF + d * 272 + p4 * 16;
            const float* src = xn + (size_t)d * Ll + p4 * 4;
            CP_ASYNC16(dst, src);
        }
        CP_COMMIT();
    }
    __syncthreads();

    if (tid < 256) {
        // ============ G1: norm-reduce + GEMM1 + softmax ============
        const int wv = tid >> 5;
        const int p0 = (wv >> 1) * 16;
        const int k0 = (wv & 1) * 32;
        const int g  = lane >> 2;
        const int tg = lane & 3;
        const int pp = tid >> 2;       // softmax pixel
        const int sg = tid & 3;        // softmax subgroup

        const uint32_t aA1b = sb + XH0_OFF +
            ((lane & 7) + ((lane >> 4) << 3)) * 144 + (p0 + ((lane >> 3) & 1) * 8) * 2;
        const uint32_t aB1 = sb + WH_OFF + (k0 + (lane & 15)) * 528 + ((lane >> 4) << 4);

        for (int t = 0; t < NTILES; ++t) {
            const int par = t & 1;
            BAR_SYNC(4 + par, NT);          // XH[par] + nrm[par] ready

            // norm reduction (warps 0,1): 1024 partials per parity
            if (tid < 64) {
                const float* nr = (const float*)(sm + NRM_OFF) + par * 1024;
                float q = 0.0f;
#pragma unroll
                for (int i = 0; i < 16; ++i) q += nr[i * 64 + tid];
                float nx = fmaxf(sqrtf(q), 1e-12f);
                ((float*)(sm + NX_OFF))[par * 64 + tid] = nx;
                RN[par * 64 + tid] = 1.0f / nx;
            }

            // GEMM1: logits_raw[p][k] = x^T W^T  (contraction d=256)
            {
                float l0[4] = {0, 0, 0, 0}, l1[4] = {0, 0, 0, 0};
                float l2[4] = {0, 0, 0, 0}, l3[4] = {0, 0, 0, 0};
                const uint32_t a1 = aA1b + (par ? XHD : 0);
#pragma unroll 4
                for (int ks = 0; ks < 16; ++ks) {
                    uint32_t A[4], B0[4], B1[4];
                    ldsm4t(A, a1 + ks * 2304);
                    ldsm4(B0, aB1 + ks * 32);
                    ldsm4(B1, aB1 + 16 * 528 + ks * 32);
                    mma_f16(l0, A, B0[0], B0[2]);
                    mma_f16(l1, A, B0[1], B0[3]);
                    mma_f16(l2, A, B1[0], B1[2]);
                    mma_f16(l3, A, B1[1], B1[3]);
                }
                int r0 = (p0 + g) * 68, r1 = (p0 + 8 + g) * 68;
                *(float2*)&Lsp[r0 + k0 + tg * 2]      = make_float2(l0[0], l0[1]);
                *(float2*)&Lsp[r1 + k0 + tg * 2]      = make_float2(l0[2], l0[3]);
                *(float2*)&Lsp[r0 + k0 + 8 + tg * 2]  = make_float2(l1[0], l1[1]);
                *(float2*)&Lsp[r1 + k0 + 8 + tg * 2]  = make_float2(l1[2], l1[3]);
                *(float2*)&Lsp[r0 + k0 + 16 + tg * 2] = make_float2(l2[0], l2[1]);
                *(float2*)&Lsp[r1 + k0 + 16 + tg * 2] = make_float2(l2[2], l2[3]);
                *(float2*)&Lsp[r0 + k0 + 24 + tg * 2] = make_float2(l3[0], l3[1]);
                *(float2*)&Lsp[r1 + k0 + 24 + tg * 2] = make_float2(l3[2], l3[3]);
            }
            BAR_ARRIVE(2 + par, NT);        // XH[par] reads done -> G2 may overwrite
            BAR_SYNC(1, 256);               // logits + RN visible within G1

            // softmax over k (4 threads per pixel), write probs*ri fp16
            // PA layout: [p][k] pitch 144B -> 2x STS.128 per thread
            {
                const float ri = RN[par * 64 + pp];
                const float* row = Lsp + pp * 68 + sg * 16;
                float e[16];
                float4 v0 = *(const float4*)(row + 0);
                float4 v1 = *(const float4*)(row + 4);
                float4 v2 = *(const float4*)(row + 8);
                float4 v3 = *(const float4*)(row + 12);
                e[0]=v0.x; e[1]=v0.y; e[2]=v0.z; e[3]=v0.w;
                e[4]=v1.x; e[5]=v1.y; e[6]=v1.z; e[7]=v1.w;
                e[8]=v2.x; e[9]=v2.y; e[10]=v2.z; e[11]=v2.w;
                e[12]=v3.x; e[13]=v3.y; e[14]=v3.z; e[15]=v3.w;
                float m = e[0];
#pragma unroll
                for (int j = 1; j < 16; ++j) m = fmaxf(m, e[j]);
                m = fmaxf(m, __shfl_xor_sync(0xffffffffu, m, 1));
                m = fmaxf(m, __shfl_xor_sync(0xffffffffu, m, 2));
                float ssum = 0.0f;
#pragma unroll
                for (int j = 0; j < 16; ++j) { e[j] = __expf(ri * (e[j] - m)); ssum += e[j]; }
                ssum += __shfl_xor_sync(0xffffffffu, ssum, 1);
                ssum += __shfl_xor_sync(0xffffffffu, ssum, 2);
                float sc = ri / ssum;
                uint32_t hb[8];
#pragma unroll
                for (int j = 0; j < 8; ++j) {
                    __half2 hv = __floats2half2_rn(e[2 * j] * sc, e[2 * j + 1] * sc);
                    hb[j] = *(uint32_t*)&hv;
                }
                char* pd = sm + (par ? PA1_OFF : PA0_OFF) + pp * 144 + sg * 32;
                *(uint4*)pd        = make_uint4(hb[0], hb[1], hb[2], hb[3]);
                *(uint4*)(pd + 16) = make_uint4(hb[4], hb[5], hb[6], hb[7]);
            }
            BAR_ARRIVE(8 + par, NT);        // PA[par] ready
            BAR_SYNC(1, 256);               // LS reads done before next GEMM1
        }
    } else {
        // ============ G2: convert + cp.async + GEMM2 + S2 ============
        const int t2 = tid - 256;
        const int pq4  = t2 & 15;      // pixel quad: p = 4*pq4 .. +3
        const int dq16 = t2 >> 4;      // 0..15, d-range dq16*16..+15
        const int d0 = ((t2 >> 5) >> 1) * 64;
        const int kq = ((t2 >> 5) & 1) * 32;
        const int g  = lane >> 2;
        const int tg = lane & 3;
        const int kS2 = t2 & 63;       // S2: fixed cluster per thread
        const int pgS2 = t2 >> 6;      // S2: pixel group (16 pixels)

        const uint32_t aA2b = sb + XH0_OFF + (d0 + (lane & 15)) * 144 + ((lane >> 4) << 4);
        // B from PA [p][k] via ldsm.trans (same address form as GEMM1's A operand)
        const uint32_t aB2b = sb + PA0_OFF +
            ((lane & 7) + ((lane >> 4) << 3)) * 144 + (kq + ((lane >> 3) & 1) * 8) * 2;

        float acc[4][4][4];
#pragma unroll
        for (int i = 0; i < 4; i++)
#pragma unroll
            for (int j = 0; j < 4; j++)
#pragma unroll
                for (int q = 0; q < 4; q++) acc[i][j][q] = 0.0f;
        float s2acc = 0.0f;

        for (int t = 0; t < NTILES; ++t) {
            const int par = t & 1;
            if (t >= 2) BAR_SYNC(2 + par, NT);   // XH[par] free
            CP_WAIT0();

            // convert XRAW -> fp16 XH[par]: 4 pixels x 16 d per thread (LDS.128/STS.64)
            {
                const char* srcb = sm + XRAW_OFF + pq4 * 16;
                char* dstb = sm + (par ? XH1_OFF : XH0_OFF) + pq4 * 8;
                float s0 = 0.0f, s1 = 0.0f, s2 = 0.0f, s3 = 0.0f;
#pragma unroll 8
                for (int j = 0; j < 16; ++j) {
                    int d = dq16 * 16 + j;
                    float4 v = *(const float4*)(srcb + d * 272);
                    s0 += v.x * v.x; s1 += v.y * v.y;
                    s2 += v.z * v.z; s3 += v.w * v.w;
                    __half2 h01 = __floats2half2_rn(v.x, v.y);
                    __half2 h23 = __floats2half2_rn(v.z, v.w);
                    *(uint2*)(dstb + d * 144) =
                        make_uint2(*(uint32_t*)&h01, *(uint32_t*)&h23);
                }
                float4* nr4 = (float4*)((float*)(sm + NRM_OFF) + par * 1024);
                nr4[dq16 * 16 + pq4] = make_float4(s0, s1, s2, s3);
            }
            BAR_SYNC(7, 256);                    // all XRAW reads done

            if (t + 1 < NTILES) {
#pragma unroll 4
                for (int i = 0; i < 16; ++i) {
                    int c = t2 + 256 * i;
                    int d = c >> 4, p4 = c & 15;
                    uint32_t dst = sb + XRAW_OFF + d * 272 + p4 * 16;
                    const float* src = xn + (size_t)d * Ll + (t + 1) * 64 + p4 * 4;
                    CP_ASYNC16(dst, src);
                }
                CP_COMMIT();
            }
            BAR_ARRIVE(4 + par, NT);             // XH[par] + nrm[par] ready

            if (t > 0) {
                const int q = par ^ 1;
                BAR_SYNC(8 + q, NT);             // PA[q] ready
                const uint32_t a2 = aA2b + (q ? XHD : 0);
                const uint32_t b2 = aB2b + (q ? PAD : 0);
#pragma unroll
                for (int ps = 0; ps < 4; ++ps) {
                    uint32_t B0[4], B1[4];
                    ldsm4t(B0, b2 + ps * 2304);
                    ldsm4t(B1, b2 + 32 + ps * 2304);
#pragma unroll
                    for (int i = 0; i < 4; ++i) {
                        uint32_t A[4];
                        ldsm4(A, a2 + i * 2304 + ps * 32);
                        mma_f16(acc[i][0], A, B0[0], B0[2]);
                        mma_f16(acc[i][1], A, B0[1], B0[3]);
                        mma_f16(acc[i][2], A, B1[0], B1[2]);
                        mma_f16(acc[i][3], A, B1[1], B1[3]);
                    }
                }
                // S2[k] += sum_p (probs*ri)[p][k] * ||x||[p]  (scalar per thread)
                {
                    const char* pab = sm + (q ? PA1_OFF : PA0_OFF) + 2 * kS2;
                    const float* nx = (const float*)(sm + NX_OFF) + q * 64 + pgS2 * 16;
#pragma unroll
                    for (int j = 0; j < 16; ++j) {
                        __half v = *(const __half*)(pab + (pgS2 * 16 + j) * 144);
                        s2acc += __half2float(v) * nx[j];
                    }
                }
            }
        }

        // tail: GEMM2 + S2 for tile 31 (par 1)
        {
            BAR_SYNC(9, NT);
            const uint32_t a2 = aA2b + XHD;
            const uint32_t b2 = aB2b + PAD;
#pragma unroll
            for (int ps = 0; ps < 4; ++ps) {
                uint32_t B0[4], B1[4];
                ldsm4t(B0, b2 + ps * 2304);
                ldsm4t(B1, b2 + 32 + ps * 2304);
#pragma unroll
                for (int i = 0; i < 4; ++i) {
                    uint32_t A[4];
                    ldsm4(A, a2 + i * 2304 + ps * 32);
                    mma_f16(acc[i][0], A, B0[0], B0[2]);
                    mma_f16(acc[i][1], A, B0[1], B0[3]);
                    mma_f16(acc[i][2], A, B1[0], B1[2]);
                    mma_f16(acc[i][3], A, B1[1], B1[3]);
                }
            }
            {
                const char* pab = sm + PA1_OFF + 2 * kS2;
                const float* nx = (const float*)(sm + NX_OFF) + 64 + pgS2 * 16;
#pragma unroll
                for (int j = 0; j < 16; ++j) {
                    __half v = *(const __half*)(pab + (pgS2 * 16 + j) * 144);
                    s2acc += __half2float(v) * nx[j];
                }
            }
        }
        // stage S2 partials (NRM region is dead now: G1 is past all nrm reads)
        ((float*)(sm + NRM_OFF))[pgS2 * 64 + kS2] = s2acc;

        // stage acc into XRAW region (only G2 touches XRAW)
        float* stg = (float*)sm;   // [64 k][260 d] f32
#pragma unroll
        for (int i = 0; i < 4; ++i)
#pragma unroll
            for (int j = 0; j < 4; ++j) {
                int d  = d0 + 16 * i + g;
                int kk = kq + 8 * j + tg * 2;
                stg[kk * 260 + d]           = acc[i][j][0];
                stg[(kk + 1) * 260 + d]     = acc[i][j][1];
                stg[kk * 260 + d + 8]       = acc[i][j][2];
                stg[(kk + 1) * 260 + d + 8] = acc[i][j][3];
            }
    }

    __syncthreads();   // staging complete (S1 + S2 partials)
    if (tid < 64) {
        const float* s2p = (const float*)(sm + NRM_OFF);
        g_S2p[hf][n][tid] = s2p[tid] + s2p[tid + 64] + s2p[tid + 128] + s2p[tid + 192];
    }
    {
        int k   = tid >> 3;
        int dq2 = (tid & 7) * 32;
        const float* stg = (const float*)sm;
#pragma unroll
        for (int jj = 0; jj < 8; ++jj) {
            float4 v = *(const float4*)&stg[k * 260 + dq2 + jj * 4];
            *(float4*)&g_S1p[hf][n][k][dq2 + jj * 4] = v;
        }
    }
}

__global__ __launch_bounds__(256)
void netvlad_finalize(const float* __restrict__ cent, float* __restrict__ out) {
    const int n = blockIdx.x;
    const int tid = threadIdx.x;
    const int w8 = tid >> 5, lane = tid & 31;
    __shared__ float s2s[64];
    __shared__ float wsum[8];
    __shared__ float ginv_s;

    if (tid < 64) s2s[tid] = g_S2p[0][n][tid] + g_S2p[1][n][tid];
    __syncthreads();

    float v[8][8];
    float gs = 0.0f;
#pragma unroll
    for (int kk = 0; kk < 8; ++kk) {
        int k = w8 * 8 + kk;
        float s2 = s2s[k];
        float loc = 0.0f;
#pragma unroll
        for (int j = 0; j < 8; ++j) {
            int d = j * 32 + lane;
            float a = g_S1p[0][n][k][d] + g_S1p[1][n][k][d] - s2 * cent[k * Dd + d];
            v[kk][j] = a;
            loc += a * a;
        }
#pragma unroll
        for (int o = 16; o > 0; o >>= 1) loc += __shfl_xor_sync(0xffffffffu, loc, o);
        float inv = 1.0f / fmaxf(sqrtf(loc), 1e-12f);
#pragma unroll
        for (int j = 0; j < 8; ++j) { v[kk][j] *= inv; gs += v[kk][j] * v[kk][j]; }
    }
#pragma unroll
    for (int o = 16; o > 0; o >>= 1) gs += __shfl_xor_sync(0xffffffffu, gs, o);
    if (lane == 0) wsum[w8] = gs;
    __syncthreads();
    if (tid == 0) {
        float t = 0.0f;
#pragma unroll
        for (int i = 0; i < 8; ++i) t += wsum[i];
        ginv_s = 1.0f / fmaxf(sqrtf(t), 1e-12f);
    }
    __syncthreads();
    float gi = ginv_s;
    size_t base = (size_t)n * Kk * Dd;
#pragma unroll
    for (int kk = 0; kk < 8; ++kk) {
        int k = w8 * 8 + kk;
#pragma unroll
        for (int j = 0; j < 8; ++j)
            out[base + (size_t)k * Dd + j * 32 + lane] = v[kk][j] * gi;
    }
}

extern "C" void kernel_launch(void* const* d_in, const int* in_sizes, int n_in,
                              void* d_out, int out_size) {
    const float* x = (const float*)d_in[0];
    const float* w = (const float*)d_in[1];
    const float* c = (const float*)d_in[2];
    float* out = (float*)d_out;

    cudaFuncSetAttribute(netvlad_mma,
                         cudaFuncAttributeMaxDynamicSharedMemorySize, SMEM_TOTAL);

    // 3-launch pattern keeps ncu (-s 5 -c 1) on netvlad_mma.
    netvlad_mma<<<2 * Nn, NT, SMEM_TOTAL>>>(x, w);
    netvlad_finalize<<<Nn, 256>>>(c, out);
    netvlad_noop<<<1, 32>>>();
}